// round 14
// baseline (speedup 1.0000x reference)
#include <cuda_runtime.h>
#include <cuda_fp16.h>
#include <cstdint>

// Problem dims
#define BB 32
#define NN 1024
#define DD 256
#define HH 512
#define HB_ELEMS (BB * NN * DD)
#define QKV_ELEMS (BB * NN * HH)
#define S_ELEMS ((long long)BB * NN * NN)
#define W1_ELEMS (HH * DD)
#define NTILE 8

// ---------------- scratch ----------------
__device__ __half g_wq16[W1_ELEMS], g_wk16[W1_ELEMS], g_wv16[W1_ELEMS];
__device__ __half g_wo16[W1_ELEMS];             // Wo hi plane only
__device__ __half g_q[QKV_ELEMS], g_k[QKV_ELEMS];
__device__ __half g_vt[QKV_ELEMS];              // [b][h][n]
__device__ __half g_e[S_ELEMS];
__device__ float  g_mloc[BB * NTILE * NN];
__device__ float  g_rsum[BB * NTILE * NN];
__device__ __half g_o2[2 * QKV_ELEMS];          // o pair (hi, lo)

// ---------------- helpers ----------------
__device__ __forceinline__ void h_split(float x, __half& h, __half& l) {
    h = __float2half_rn(x);
    l = __float2half_rn(x - __half2float(h));
}
__device__ __forceinline__ uint32_t packh2(__half a, __half b) {
    __half2 t = __halves2half2(a, b);
    return *reinterpret_cast<uint32_t*>(&t);
}
__device__ __forceinline__ uint32_t mulh2(uint32_t a, __half2 s) {
    __half2 x = *reinterpret_cast<__half2*>(&a);
    x = __hmul2(x, s);
    return *reinterpret_cast<uint32_t*>(&x);
}
__device__ __forceinline__ uint32_t smem_u32(const void* p) {
    uint32_t a;
    asm("{ .reg .u64 t; cvta.to.shared.u64 t, %1; cvt.u32.u64 %0, t; }" : "=r"(a) : "l"(p));
    return a;
}
__device__ __forceinline__ void cp16(uint32_t dst, const void* src) {
    asm volatile("cp.async.cg.shared.global [%0], [%1], 16;" :: "r"(dst), "l"(src));
}
#define CP_COMMIT() asm volatile("cp.async.commit_group;" ::: "memory")
#define CP_WAIT(n)  asm volatile("cp.async.wait_group %0;" :: "n"(n) : "memory")

__device__ __forceinline__ void ldsm4(uint32_t* r, uint32_t addr) {
    asm volatile("ldmatrix.sync.aligned.m8n8.x4.shared.b16 {%0,%1,%2,%3}, [%4];"
        : "=r"(r[0]), "=r"(r[1]), "=r"(r[2]), "=r"(r[3]) : "r"(addr));
}
__device__ __forceinline__ void mma_f16(float* d, const uint32_t* a, const uint32_t* b) {
    asm volatile(
        "mma.sync.aligned.m16n8k16.row.col.f32.f16.f16.f32 "
        "{%0,%1,%2,%3}, {%4,%5,%6,%7}, {%8,%9}, {%0,%1,%2,%3};"
        : "+f"(d[0]), "+f"(d[1]), "+f"(d[2]), "+f"(d[3])
        : "r"(a[0]), "r"(a[1]), "r"(a[2]), "r"(a[3]), "r"(b[0]), "r"(b[1]));
}

// ---------------- tile config ----------------
#define BM 128
#define BN 128
#define THREADS 256

// single-plane GEMMs: BK=64, pitch 144 B, 3 stages, 2 CTAs/SM
#define BK64 64
#define PITCH64 144
#define PLANE64 (128 * PITCH64)          // 18432 B
#define SSTAGES 3
#define SSTAGE_B (2 * PLANE64)           // 36864
#define SSMEM (SSTAGES * SSTAGE_B)       // 110592

// p3 GEMM (out-proj, 2-MMA): 3 planes (Ah, Al, B), BK=64, 2 stages, 2 CTAs/SM
#define P3STAGES 2
#define P3STAGE_B (3 * PLANE64)          // 55296
#define P3SMEM (P3STAGES * P3STAGE_B)    // 110592

// transposed-epilogue staging pitch (halves)
#define PT 132

// ---- mainloop load macro (BK=64 single-plane, 256 threads, both cp.async) ----
#define ISSUE64(Ab, Bb, Kdim, it)                                              \
    do {                                                                       \
        const int s_ = (it) % SSTAGES;                                         \
        const int k0_ = (it) * BK64;                                           \
        const uint32_t stg_ = sbase + s_ * SSTAGE_B;                           \
        _Pragma("unroll")                                                      \
        for (int c_ = 0; c_ < 8; c_++) {                                       \
            const int id_ = tid + c_ * 256;                                    \
            const int seg_ = id_ >> 10;                                        \
            const int rid_ = id_ & 1023;                                       \
            const int row_ = rid_ >> 3, ch_ = rid_ & 7;                        \
            const __half* src_ = seg_ ? (Bb + (long long)(n0 + row_) * Kdim)   \
                                      : (Ab + (long long)(m0 + row_) * Kdim);  \
            cp16(stg_ + seg_ * PLANE64 + row_ * PITCH64 + ch_ * 16,            \
                 src_ + k0_ + ch_ * 8);                                        \
        }                                                                      \
    } while (0)

// ===========================================================================
// Fused Q/K/V projection (8 warps, 32x64 warp tiles)
// A-plane: inline fp32 h -> fp16 conversion (LDG + CVT + STS); B: cp.async.
// ===========================================================================
__global__ __launch_bounds__(THREADS, 2) void gemm_proj(
    const float* __restrict__ Hf,
    const __half* __restrict__ Wqp, const __half* __restrict__ Wkp,
    const __half* __restrict__ Wvp,
    const float* __restrict__ bqp, const float* __restrict__ bkp,
    const float* __restrict__ bvp,
    __half* __restrict__ Qp, __half* __restrict__ Kp, __half* __restrict__ Vtp)
{
    extern __shared__ char smc[];
    const uint32_t sbase = smem_u32(smc);

    const int tid = threadIdx.x;
    const int wid = tid >> 5;
    const int lane = tid & 31;
    const int g = lane >> 2;
    const int t = lane & 3;
    const int z = blockIdx.z;

    const __half* Bb = (z == 0) ? Wqp : (z == 1) ? Wkp : Wvp;
    const float* bias = (z == 0) ? bqp : (z == 1) ? bkp : bvp;

    const int m0 = blockIdx.y * BM;
    const int n0 = blockIdx.x * BN;
    const int wm = (wid & 3) * 32;
    const int wn = (wid >> 2) * 64;
    const int K = DD, N = HH;

    float acc[2][8][4];
#pragma unroll
    for (int i = 0; i < 2; i++)
#pragma unroll
        for (int j = 0; j < 8; j++)
#pragma unroll
            for (int r = 0; r < 4; r++) acc[i][j][r] = 0.0f;

    const int niter = K / BK64;     // 4

    // A plane: LDG fp32 -> convert -> STS fp16 (1024 x 16B-out chunks)
    auto issue_A = [&](int it) {
        const int s = it % SSTAGES;
        const int k0 = it * BK64;
        char* stg = smc + s * SSTAGE_B;
#pragma unroll
        for (int c = 0; c < 4; c++) {
            const int id = tid + c * 256;
            const int row = id >> 3, ch = id & 7;
            const float* hp = Hf + (long long)(m0 + row) * K + k0 + ch * 8;
            float4 v0 = *(const float4*)hp;
            float4 v1 = *(const float4*)(hp + 4);
            uint4 w;
            w.x = packh2(__float2half_rn(v0.x), __float2half_rn(v0.y));
            w.y = packh2(__float2half_rn(v0.z), __float2half_rn(v0.w));
            w.z = packh2(__float2half_rn(v1.x), __float2half_rn(v1.y));
            w.w = packh2(__float2half_rn(v1.z), __float2half_rn(v1.w));
            *(uint4*)(stg + row * PITCH64 + ch * 16) = w;
        }
    };
    // B plane: cp.async fp16 weights (1024 x 16B chunks)
    auto issue_B = [&](int it) {
        const int s = it % SSTAGES;
        const int k0 = it * BK64;
        const uint32_t stg = sbase + s * SSTAGE_B + PLANE64;
#pragma unroll
        for (int c = 0; c < 4; c++) {
            const int id = tid + c * 256;
            const int row = id >> 3, ch = id & 7;
            cp16(stg + row * PITCH64 + ch * 16,
                 Bb + (long long)(n0 + row) * K + k0 + ch * 8);
        }
    };

#pragma unroll
    for (int it = 0; it < SSTAGES - 1; it++) {
        issue_A(it); issue_B(it); CP_COMMIT();
    }

    const int a_row = lane & 15;
    const int a_kc = (lane >> 4) * 8;
    const int b_n = ((lane >> 4) << 3) + (lane & 7);
    const int b_kc = ((lane >> 3) & 1) * 8;

    for (int it = 0; it < niter; it++) {
        CP_WAIT(SSTAGES - 2);
        __syncthreads();
        if (it + SSTAGES - 1 < niter) { issue_A(it + SSTAGES - 1); issue_B(it + SSTAGES - 1); }
        CP_COMMIT();

        const uint32_t stg = sbase + (it % SSTAGES) * SSTAGE_B;
#pragma unroll
        for (int kk = 0; kk < BK64; kk += 16) {
            uint32_t Af[2][4];
#pragma unroll
            for (int i = 0; i < 2; i++)
                ldsm4(Af[i], stg + (uint32_t)(wm + i * 16 + a_row) * PITCH64
                               + (uint32_t)(kk + a_kc) * 2);
#pragma unroll
            for (int p = 0; p < 4; p++) {
                uint32_t Bf[4];
                ldsm4(Bf, stg + PLANE64 + (uint32_t)(wn + p * 16 + b_n) * PITCH64
                                        + (uint32_t)(kk + b_kc) * 2);
#pragma unroll
                for (int i = 0; i < 2; i++) {
                    mma_f16(acc[i][2 * p],     Af[i], &Bf[0]);
                    mma_f16(acc[i][2 * p + 1], Af[i], &Bf[2]);
                }
            }
        }
    }

    if (z < 2) {
        __half* C = (z == 0) ? Qp : Kp;
#pragma unroll
        for (int i = 0; i < 2; i++) {
            const int r0 = m0 + wm + i * 16 + g;
#pragma unroll
            for (int j = 0; j < 8; j++) {
                const int cc = n0 + wn + j * 8 + 2 * t;
                float b0 = bias[cc], b1 = bias[cc + 1];
                float x0 = fmaxf(acc[i][j][0] + b0, 0.f);
                float x1 = fmaxf(acc[i][j][1] + b1, 0.f);
                float x2 = fmaxf(acc[i][j][2] + b0, 0.f);
                float x3 = fmaxf(acc[i][j][3] + b1, 0.f);
                *(uint32_t*)(C + (long long)r0 * N + cc) =
                    packh2(__float2half_rn(x0), __float2half_rn(x1));
                *(uint32_t*)(C + (long long)(r0 + 8) * N + cc) =
                    packh2(__float2half_rn(x2), __float2half_rn(x3));
            }
        }
    } else {
        // V: stage tile in smem, write transposed vt[b][h][n]
        __syncthreads();
        __half* tile = (__half*)smc;
#pragma unroll
        for (int i = 0; i < 2; i++) {
            const int rl0 = wm + i * 16 + g;
#pragma unroll
            for (int j = 0; j < 8; j++) {
                const int cl = wn + j * 8 + 2 * t;
                float b0 = bias[n0 + cl], b1 = bias[n0 + cl + 1];
                tile[rl0 * PT + cl]           = __float2half_rn(fmaxf(acc[i][j][0] + b0, 0.f));
                tile[rl0 * PT + cl + 1]       = __float2half_rn(fmaxf(acc[i][j][1] + b1, 0.f));
                tile[(rl0 + 8) * PT + cl]     = __float2half_rn(fmaxf(acc[i][j][2] + b0, 0.f));
                tile[(rl0 + 8) * PT + cl + 1] = __float2half_rn(fmaxf(acc[i][j][3] + b1, 0.f));
            }
        }
        __syncthreads();
        const int b = m0 >> 10;
        const int nloc = m0 & 1023;
        __half* vtb = Vtp + (long long)b * HH * NN + nloc;
        const int g2 = tid >> 7;
        const int l128 = tid & 127;
#pragma unroll
        for (int jc = 0; jc < 64; jc++) {
            const int c = g2 * 64 + jc;
            vtb[(long long)(n0 + c) * NN + l128] = tile[l128 * PT + c];
        }
    }
}

// ===========================================================================
// S GEMM with online-exp epilogue (8 warps, 32x64)
// ===========================================================================
__global__ __launch_bounds__(THREADS, 2) void gemm_qk(
    const __half* __restrict__ Q, const __half* __restrict__ Kx,
    __half* __restrict__ E, float* __restrict__ mloc, float* __restrict__ rsum)
{
    extern __shared__ char smc[];
    __shared__ float sred[2][128];
    const uint32_t sbase = smem_u32(smc);

    const int tid = threadIdx.x;
    const int wid = tid >> 5;
    const int lane = tid & 31;
    const int g = lane >> 2;
    const int t = lane & 3;
    const int bz = blockIdx.z;

    const __half* Ab = Q + ((long long)bz * NN * HH);
    const __half* Bb = Kx + ((long long)bz * NN * HH);
    const int m0 = blockIdx.y * BM;
    const int n0 = blockIdx.x * BN;
    const int wm = (wid & 3) * 32;
    const int wn = (wid >> 2) * 64;
    const int K = HH;

    float acc[2][8][4];
#pragma unroll
    for (int i = 0; i < 2; i++)
#pragma unroll
        for (int j = 0; j < 8; j++)
#pragma unroll
            for (int r = 0; r < 4; r++) acc[i][j][r] = 0.0f;

    const int niter = K / BK64;   // 8

#pragma unroll
    for (int it = 0; it < SSTAGES - 1; it++) { ISSUE64(Ab, Bb, K, it); CP_COMMIT(); }

    const int a_row = lane & 15;
    const int a_kc = (lane >> 4) * 8;
    const int b_n = ((lane >> 4) << 3) + (lane & 7);
    const int b_kc = ((lane >> 3) & 1) * 8;

    for (int it = 0; it < niter; it++) {
        CP_WAIT(SSTAGES - 2);
        __syncthreads();
        if (it + SSTAGES - 1 < niter) { ISSUE64(Ab, Bb, K, it + SSTAGES - 1); }
        CP_COMMIT();

        const uint32_t stg = sbase + (it % SSTAGES) * SSTAGE_B;
#pragma unroll
        for (int kk = 0; kk < BK64; kk += 16) {
            uint32_t Af[2][4];
#pragma unroll
            for (int i = 0; i < 2; i++)
                ldsm4(Af[i], stg + (uint32_t)(wm + i * 16 + a_row) * PITCH64
                               + (uint32_t)(kk + a_kc) * 2);
#pragma unroll
            for (int p = 0; p < 4; p++) {
                uint32_t Bf[4];
                ldsm4(Bf, stg + PLANE64 + (uint32_t)(wn + p * 16 + b_n) * PITCH64
                                        + (uint32_t)(kk + b_kc) * 2);
#pragma unroll
                for (int i = 0; i < 2; i++) {
                    mma_f16(acc[i][2 * p],     Af[i], &Bf[0]);
                    mma_f16(acc[i][2 * p + 1], Af[i], &Bf[2]);
                }
            }
        }
    }

    // ---- online-exp epilogue (bit-exact order) ----
    const int R0 = wm + g, R1 = wm + g + 8, R2 = wm + 16 + g, R3 = wm + 24 + g;
    const int half = wid >> 2;

    float rm[4] = {-1e30f, -1e30f, -1e30f, -1e30f};
#pragma unroll
    for (int j = 0; j < 8; j++) {
        rm[0] = fmaxf(rm[0], fmaxf(acc[0][j][0], acc[0][j][1]));
        rm[1] = fmaxf(rm[1], fmaxf(acc[0][j][2], acc[0][j][3]));
        rm[2] = fmaxf(rm[2], fmaxf(acc[1][j][0], acc[1][j][1]));
        rm[3] = fmaxf(rm[3], fmaxf(acc[1][j][2], acc[1][j][3]));
    }
#pragma unroll
    for (int o = 1; o <= 2; o <<= 1)
#pragma unroll
        for (int k = 0; k < 4; k++)
            rm[k] = fmaxf(rm[k], __shfl_xor_sync(0xffffffffu, rm[k], o));

    __syncthreads();
    if (t == 0) {
        sred[half][R0] = rm[0]; sred[half][R1] = rm[1];
        sred[half][R2] = rm[2]; sred[half][R3] = rm[3];
    }
    __syncthreads();
    float gm[4];
    gm[0] = fmaxf(sred[0][R0], sred[1][R0]);
    gm[1] = fmaxf(sred[0][R1], sred[1][R1]);
    gm[2] = fmaxf(sred[0][R2], sred[1][R2]);
    gm[3] = fmaxf(sred[0][R3], sred[1][R3]);
    __syncthreads();

    float rs[4] = {0.f, 0.f, 0.f, 0.f};
#pragma unroll
    for (int j = 0; j < 8; j++) {
        acc[0][j][0] = __expf(acc[0][j][0] - gm[0]);
        acc[0][j][1] = __expf(acc[0][j][1] - gm[0]);
        rs[0] += acc[0][j][0] + acc[0][j][1];
        acc[0][j][2] = __expf(acc[0][j][2] - gm[1]);
        acc[0][j][3] = __expf(acc[0][j][3] - gm[1]);
        rs[1] += acc[0][j][2] + acc[0][j][3];
        acc[1][j][0] = __expf(acc[1][j][0] - gm[2]);
        acc[1][j][1] = __expf(acc[1][j][1] - gm[2]);
        rs[2] += acc[1][j][0] + acc[1][j][1];
        acc[1][j][2] = __expf(acc[1][j][2] - gm[3]);
        acc[1][j][3] = __expf(acc[1][j][3] - gm[3]);
        rs[3] += acc[1][j][2] + acc[1][j][3];
    }
#pragma unroll
    for (int o = 1; o <= 2; o <<= 1)
#pragma unroll
        for (int k = 0; k < 4; k++)
            rs[k] += __shfl_xor_sync(0xffffffffu, rs[k], o);

    if (t == 0 && half == 0) {
        sred[0][R0] = rs[0]; sred[0][R1] = rs[1];
        sred[0][R2] = rs[2]; sred[0][R3] = rs[3];
    }
    __syncthreads();
    if (t == 0 && half == 1) {
        atomicAdd(&sred[0][R0], rs[0]); atomicAdd(&sred[0][R1], rs[1]);
        atomicAdd(&sred[0][R2], rs[2]); atomicAdd(&sred[0][R3], rs[3]);
    }
    __syncthreads();

    if (t == 0 && half == 0) {
        const long long sb = ((long long)(bz * NTILE + blockIdx.x) << 10) + m0;
        mloc[sb + R0] = gm[0]; rsum[sb + R0] = sred[0][R0];
        mloc[sb + R1] = gm[1]; rsum[sb + R1] = sred[0][R1];
        mloc[sb + R2] = gm[2]; rsum[sb + R2] = sred[0][R2];
        mloc[sb + R3] = gm[3]; rsum[sb + R3] = sred[0][R3];
    }

    __half* Eb = E + ((long long)bz << 20);
#pragma unroll
    for (int i = 0; i < 2; i++) {
        const int r0 = m0 + wm + i * 16 + g;
#pragma unroll
        for (int j = 0; j < 8; j++) {
            const int cc = n0 + wn + j * 8 + 2 * t;
            *(uint32_t*)(Eb + (long long)r0 * NN + cc) =
                packh2(__float2half_rn(acc[i][j][0]), __float2half_rn(acc[i][j][1]));
            *(uint32_t*)(Eb + (long long)(r0 + 8) * NN + cc) =
                packh2(__float2half_rn(acc[i][j][2]), __float2half_rn(acc[i][j][3]));
        }
    }
}

// ===========================================================================
// O GEMM: O = (diag-scaled E) * Vt^T -> half-pair, stats inlined
// ===========================================================================
__global__ __launch_bounds__(THREADS, 2) void gemm_pv(
    const __half* __restrict__ E, const __half* __restrict__ Vt,
    const float* __restrict__ mloc, const float* __restrict__ rsum,
    __half* __restrict__ O2, long long sPC)
{
    extern __shared__ char smc[];
    __shared__ float sscl[NTILE][128];
    const uint32_t sbase = smem_u32(smc);

    const int tid = threadIdx.x;
    const int wid = tid >> 5;
    const int lane = tid & 31;
    const int g = lane >> 2;
    const int t = lane & 3;
    const int bz = blockIdx.z;

    const __half* Ab = E + ((long long)bz << 20);
    const __half* Bb = Vt + ((long long)bz * HH * NN);
    const int m0 = blockIdx.y * BM;
    const int n0 = blockIdx.x * BN;
    const int wm = (wid & 3) * 32;
    const int wn = (wid >> 2) * 64;
    const int N = HH, K = NN;

    // inline stats (identical op order)
    if (tid < 128) {
        const int r = m0 + tid;
        float m[NTILE], s[NTILE];
        float M = -1e30f;
#pragma unroll
        for (int tt = 0; tt < NTILE; tt++) {
            const long long p = ((long long)(bz * NTILE + tt) << 10) + r;
            m[tt] = mloc[p]; s[tt] = rsum[p];
            M = fmaxf(M, m[tt]);
        }
        float denom = 0.f;
#pragma unroll
        for (int tt = 0; tt < NTILE; tt++) {
            m[tt] = __expf(m[tt] - M);
            denom += s[tt] * m[tt];
        }
        const float inv = 1.0f / denom;
#pragma unroll
        for (int tt = 0; tt < NTILE; tt++)
            sscl[tt][tid] = m[tt] * inv;
    }

    float acc[2][8][4];
#pragma unroll
    for (int i = 0; i < 2; i++)
#pragma unroll
        for (int j = 0; j < 8; j++)
#pragma unroll
            for (int r = 0; r < 4; r++) acc[i][j][r] = 0.0f;

    const int niter = K / BK64;   // 16

#pragma unroll
    for (int it = 0; it < SSTAGES - 1; it++) { ISSUE64(Ab, Bb, K, it); CP_COMMIT(); }
    __syncthreads();   // sscl ready

    const int a_row = lane & 15;
    const int a_kc = (lane >> 4) * 8;
    const int b_n = ((lane >> 4) << 3) + (lane & 7);
    const int b_kc = ((lane >> 3) & 1) * 8;

    const int R0 = wm + g, R1 = wm + g + 8, R2 = wm + 16 + g, R3 = wm + 24 + g;
    __half2 hs[4];

    for (int it = 0; it < niter; it++) {
        CP_WAIT(SSTAGES - 2);
        __syncthreads();
        if (it + SSTAGES - 1 < niter) { ISSUE64(Ab, Bb, K, it + SSTAGES - 1); }
        CP_COMMIT();

        if ((it & 1) == 0) {
            const int tt = it >> 1;
            hs[0] = __float2half2_rn(sscl[tt][R0]);
            hs[1] = __float2half2_rn(sscl[tt][R1]);
            hs[2] = __float2half2_rn(sscl[tt][R2]);
            hs[3] = __float2half2_rn(sscl[tt][R3]);
        }

        const uint32_t stg = sbase + (it % SSTAGES) * SSTAGE_B;
#pragma unroll
        for (int kk = 0; kk < BK64; kk += 16) {
            uint32_t Af[2][4];
#pragma unroll
            for (int i = 0; i < 2; i++) {
                ldsm4(Af[i], stg + (uint32_t)(wm + i * 16 + a_row) * PITCH64
                               + (uint32_t)(kk + a_kc) * 2);
                Af[i][0] = mulh2(Af[i][0], hs[2 * i]);
                Af[i][1] = mulh2(Af[i][1], hs[2 * i + 1]);
                Af[i][2] = mulh2(Af[i][2], hs[2 * i]);
                Af[i][3] = mulh2(Af[i][3], hs[2 * i + 1]);
            }
#pragma unroll
            for (int p = 0; p < 4; p++) {
                uint32_t Bf[4];
                ldsm4(Bf, stg + PLANE64 + (uint32_t)(wn + p * 16 + b_n) * PITCH64
                                        + (uint32_t)(kk + b_kc) * 2);
#pragma unroll
                for (int i = 0; i < 2; i++) {
                    mma_f16(acc[i][2 * p],     Af[i], &Bf[0]);
                    mma_f16(acc[i][2 * p + 1], Af[i], &Bf[2]);
                }
            }
        }
    }

    __half* Ch = O2 + (long long)bz * NN * HH;
    __half* Cl = Ch + sPC;
#pragma unroll
    for (int i = 0; i < 2; i++) {
        const int r0 = m0 + wm + i * 16 + g;
#pragma unroll
        for (int j = 0; j < 8; j++) {
            const int cc = n0 + wn + j * 8 + 2 * t;
            __half h0, l0, h1, l1, h2, l2, h3, l3;
            h_split(acc[i][j][0], h0, l0); h_split(acc[i][j][1], h1, l1);
            h_split(acc[i][j][2], h2, l2); h_split(acc[i][j][3], h3, l3);
            *(uint32_t*)(Ch + (long long)r0 * N + cc)       = packh2(h0, h1);
            *(uint32_t*)(Cl + (long long)r0 * N + cc)       = packh2(l0, l1);
            *(uint32_t*)(Ch + (long long)(r0 + 8) * N + cc) = packh2(h2, h3);
            *(uint32_t*)(Cl + (long long)(r0 + 8) * N + cc) = packh2(l2, l3);
        }
    }
}

// ===========================================================================
// Out-proj GEMM (2 MMAs): out = relu((o_hi + o_lo) Wo_hi^T + bo), fp32 out.
// ===========================================================================
__global__ __launch_bounds__(THREADS, 2) void gemm_p3(
    const __half* __restrict__ A, const __half* __restrict__ B,
    const float* __restrict__ bias, float* __restrict__ C,
    int M, int N, int K, long long sPA)
{
    extern __shared__ char smc[];
    const uint32_t sbase = smem_u32(smc);

    const int tid = threadIdx.x;
    const int wid = tid >> 5;
    const int lane = tid & 31;
    const int g = lane >> 2;
    const int t = lane & 3;

    const __half* Ah = A;
    const __half* Al = A + sPA;
    const int m0 = blockIdx.y * BM;
    const int n0 = blockIdx.x * BN;
    const int wm = (wid & 3) * 32;
    const int wn = (wid >> 2) * 64;

    float acc[2][8][4];
#pragma unroll
    for (int i = 0; i < 2; i++)
#pragma unroll
        for (int j = 0; j < 8; j++)
#pragma unroll
            for (int r = 0; r < 4; r++) acc[i][j][r] = 0.0f;

    const int niter = K / BK64;   // 8

    auto issue_loads = [&](int it) {
        const int s = it % P3STAGES;
        const int k0 = it * BK64;
        const uint32_t stg = sbase + s * P3STAGE_B;
#pragma unroll
        for (int c = 0; c < 12; c++) {
            const int id = tid + c * 256;
            const int seg = id >> 10;
            const int rid = id & 1023;
            const int row = rid >> 3, ch = rid & 7;
            const __half* src = (seg == 0) ? (Ah + (long long)(m0 + row) * K)
                              : (seg == 1) ? (Al + (long long)(m0 + row) * K)
                                           : (B  + (long long)(n0 + row) * K);
            cp16(stg + seg * PLANE64 + row * PITCH64 + ch * 16,
                 src + k0 + ch * 8);
        }
    };

#pragma unroll
    for (int it = 0; it < P3STAGES - 1; it++) { issue_loads(it); CP_COMMIT(); }

    const int a_row = lane & 15;
    const int a_kc = (lane >> 4) * 8;
    const int b_n = ((lane >> 4) << 3) + (lane & 7);
    const int b_kc = ((lane >> 3) & 1) * 8;

    for (int it = 0; it < niter; it++) {
        CP_WAIT(P3STAGES - 2);
        __syncthreads();
        if (it + P3STAGES - 1 < niter) issue_loads(it + P3STAGES - 1);
        CP_COMMIT();

        const uint32_t stg = sbase + (it % P3STAGES) * P3STAGE_B;
#pragma unroll
        for (int kk = 0; kk < BK64; kk += 16) {
            uint32_t Afh[2][4], Afl[2][4];
#pragma unroll
            for (int i = 0; i < 2; i++) {
                const uint32_t ao = (uint32_t)(wm + i * 16 + a_row) * PITCH64
                                  + (uint32_t)(kk + a_kc) * 2;
                ldsm4(Afh[i], stg + ao);
                ldsm4(Afl[i], stg + PLANE64 + ao);
            }
#pragma unroll
            for (int p = 0; p < 4; p++) {
                uint32_t Bf[4];
                ldsm4(Bf, stg + 2 * PLANE64
                         + (uint32_t)(wn + p * 16 + b_n) * PITCH64
                         + (uint32_t)(kk + b_kc) * 2);
#pragma unroll
                for (int i = 0; i < 2; i++) {
                    mma_f16(acc[i][2 * p],     Afh[i], &Bf[0]);
                    mma_f16(acc[i][2 * p],     Afl[i], &Bf[0]);
                    mma_f16(acc[i][2 * p + 1], Afh[i], &Bf[2]);
                    mma_f16(acc[i][2 * p + 1], Afl[i], &Bf[2]);
                }
            }
        }
    }

#pragma unroll
    for (int i = 0; i < 2; i++) {
        const int r0 = m0 + wm + i * 16 + g;
#pragma unroll
        for (int j = 0; j < 8; j++) {
            const int cc = n0 + wn + j * 8 + 2 * t;
            float b0 = bias[cc], b1 = bias[cc + 1];
            *(float2*)(C + (long long)r0 * N + cc) =
                make_float2(fmaxf(acc[i][j][0] + b0, 0.f), fmaxf(acc[i][j][1] + b1, 0.f));
            *(float2*)(C + (long long)(r0 + 8) * N + cc) =
                make_float2(fmaxf(acc[i][j][2] + b0, 0.f), fmaxf(acc[i][j][3] + b1, 0.f));
        }
    }
}

// ---------------------------------------------------------------------------
// pack: 4 weight matrices -> fp16 (h is converted inline in gemm_proj)
// ---------------------------------------------------------------------------
#define PK_W (W1_ELEMS / 4)
__global__ __launch_bounds__(256) void pack_w(
    const float* __restrict__ Wq, const float* __restrict__ Wk,
    const float* __restrict__ Wv, const float* __restrict__ Wo,
    __half* __restrict__ wq16, __half* __restrict__ wk16,
    __half* __restrict__ wv16, __half* __restrict__ wo16)
{
    const int total = 4 * PK_W;
    for (int i = blockIdx.x * blockDim.x + threadIdx.x; i < total;
         i += gridDim.x * blockDim.x) {
        int seg = i / PK_W, idx = i % PK_W;
        const float* src = (seg == 0) ? Wq : (seg == 1) ? Wk : (seg == 2) ? Wv : Wo;
        __half* dst = (seg == 0) ? wq16 : (seg == 1) ? wk16 : (seg == 2) ? wv16 : wo16;
        float4 v = ((const float4*)src)[idx];
        ((uint2*)dst)[idx] = make_uint2(
            packh2(__float2half_rn(v.x), __float2half_rn(v.y)),
            packh2(__float2half_rn(v.z), __float2half_rn(v.w)));
    }
}

// ---------------------------------------------------------------------------
// kernel_launch — inputs: h, Wv, bv, Wk, bk, Wq, bq, Wo, bo
// ---------------------------------------------------------------------------
extern "C" void kernel_launch(void* const* d_in, const int* in_sizes, int n_in,
                              void* d_out, int out_size)
{
    const float* h  = (const float*)d_in[0];
    const float* Wv = (const float*)d_in[1];
    const float* bv = (const float*)d_in[2];
    const float* Wk = (const float*)d_in[3];
    const float* bk = (const float*)d_in[4];
    const float* Wq = (const float*)d_in[5];
    const float* bq = (const float*)d_in[6];
    const float* Wo = (const float*)d_in[7];
    const float* bo = (const float*)d_in[8];
    float* out = (float*)d_out;

    __half *wq16, *wk16, *wv16, *wo16, *q, *k, *vt, *e, *o2;
    float *mloc, *rsum;
    cudaGetSymbolAddress((void**)&wq16, g_wq16);
    cudaGetSymbolAddress((void**)&wk16, g_wk16);
    cudaGetSymbolAddress((void**)&wv16, g_wv16);
    cudaGetSymbolAddress((void**)&wo16, g_wo16);
    cudaGetSymbolAddress((void**)&q,    g_q);
    cudaGetSymbolAddress((void**)&k,    g_k);
    cudaGetSymbolAddress((void**)&vt,   g_vt);
    cudaGetSymbolAddress((void**)&e,    g_e);
    cudaGetSymbolAddress((void**)&mloc, g_mloc);
    cudaGetSymbolAddress((void**)&rsum, g_rsum);
    cudaGetSymbolAddress((void**)&o2,   g_o2);

    cudaFuncSetAttribute(gemm_proj, cudaFuncAttributeMaxDynamicSharedMemorySize, SSMEM);
    cudaFuncSetAttribute(gemm_qk,   cudaFuncAttributeMaxDynamicSharedMemorySize, SSMEM);
    cudaFuncSetAttribute(gemm_pv,   cudaFuncAttributeMaxDynamicSharedMemorySize, SSMEM);
    cudaFuncSetAttribute(gemm_p3,   cudaFuncAttributeMaxDynamicSharedMemorySize, P3SMEM);

    const int M = BB * NN;   // 32768

    // 1. pack weights only (h converted inline in proj)
    pack_w<<<512, 256>>>(Wq, Wk, Wv, Wo, wq16, wk16, wv16, wo16);

    // 2. fused Q/K/V projections; z==2 writes vt directly
    {
        dim3 grid(HH / BN, M / BM, 3);
        gemm_proj<<<grid, THREADS, SSMEM>>>(h, wq16, wk16, wv16,
                                            bq, bk, bv, q, k, vt);
    }

    // 3. S GEMM + online exp -> e fp16 + per-tile stats
    {
        dim3 grid(NN / BN, NN / BM, BB);
        gemm_qk<<<grid, THREADS, SSMEM>>>(q, k, e, mloc, rsum);
    }

    // 4. O = scaled-E * Vt^T -> fp16 pair (stats inlined)
    {
        dim3 grid(HH / BN, NN / BM, BB);
        gemm_pv<<<grid, THREADS, SSMEM>>>(e, vt, mloc, rsum, o2, QKV_ELEMS);
    }

    // 5. out = relu(O Wo^T + bo) -> fp32  (2-MMA pair-A GEMM)
    {
        dim3 grid(DD / BN, M / BM, 1);
        gemm_p3<<<grid, THREADS, P3SMEM>>>(o2, wo16, bo, out, M, DD, HH,
                                           QKV_ELEMS);
    }
}

// round 15
// speedup vs baseline: 1.0573x; 1.0573x over previous
#include <cuda_runtime.h>
#include <cuda_fp16.h>
#include <cstdint>

// Problem dims
#define BB 32
#define NN 1024
#define DD 256
#define HH 512
#define HB_ELEMS (BB * NN * DD)
#define QKV_ELEMS (BB * NN * HH)
#define S_ELEMS ((long long)BB * NN * NN)
#define W1_ELEMS (HH * DD)
#define NTILE 8

// ---------------- scratch ----------------
__device__ __half g_h16[HB_ELEMS];
__device__ __half g_wq16[W1_ELEMS], g_wk16[W1_ELEMS], g_wv16[W1_ELEMS];
__device__ __half g_wo16[W1_ELEMS];             // Wo hi plane only
__device__ __half g_q[QKV_ELEMS], g_k[QKV_ELEMS];
__device__ __half g_vt[QKV_ELEMS];              // [b][h][n]
__device__ __half g_e[S_ELEMS];
__device__ float  g_mloc[BB * NTILE * NN];
__device__ float  g_rsum[BB * NTILE * NN];
__device__ __half g_o2[2 * QKV_ELEMS];          // o pair (hi, lo)

// ---------------- helpers ----------------
__device__ __forceinline__ void h_split(float x, __half& h, __half& l) {
    h = __float2half_rn(x);
    l = __float2half_rn(x - __half2float(h));
}
__device__ __forceinline__ uint32_t packh2(__half a, __half b) {
    __half2 t = __halves2half2(a, b);
    return *reinterpret_cast<uint32_t*>(&t);
}
__device__ __forceinline__ uint32_t mulh2(uint32_t a, __half2 s) {
    __half2 x = *reinterpret_cast<__half2*>(&a);
    x = __hmul2(x, s);
    return *reinterpret_cast<uint32_t*>(&x);
}
__device__ __forceinline__ uint32_t smem_u32(const void* p) {
    uint32_t a;
    asm("{ .reg .u64 t; cvta.to.shared.u64 t, %1; cvt.u32.u64 %0, t; }" : "=r"(a) : "l"(p));
    return a;
}
__device__ __forceinline__ void cp16(uint32_t dst, const void* src) {
    asm volatile("cp.async.cg.shared.global [%0], [%1], 16;" :: "r"(dst), "l"(src));
}
#define CP_COMMIT() asm volatile("cp.async.commit_group;" ::: "memory")
#define CP_WAIT(n)  asm volatile("cp.async.wait_group %0;" :: "n"(n) : "memory")

__device__ __forceinline__ void ldsm4(uint32_t* r, uint32_t addr) {
    asm volatile("ldmatrix.sync.aligned.m8n8.x4.shared.b16 {%0,%1,%2,%3}, [%4];"
        : "=r"(r[0]), "=r"(r[1]), "=r"(r[2]), "=r"(r[3]) : "r"(addr));
}
__device__ __forceinline__ void mma_f16(float* d, const uint32_t* a, const uint32_t* b) {
    asm volatile(
        "mma.sync.aligned.m16n8k16.row.col.f32.f16.f16.f32 "
        "{%0,%1,%2,%3}, {%4,%5,%6,%7}, {%8,%9}, {%0,%1,%2,%3};"
        : "+f"(d[0]), "+f"(d[1]), "+f"(d[2]), "+f"(d[3])
        : "r"(a[0]), "r"(a[1]), "r"(a[2]), "r"(a[3]), "r"(b[0]), "r"(b[1]));
}

// ---------------- tile config ----------------
#define BM 128
#define BN 128
#define THREADS 256

// single-plane GEMMs: BK=64, pitch 144 B, 3 stages, 2 CTAs/SM
#define BK64 64
#define PITCH64 144
#define PLANE64 (128 * PITCH64)          // 18432 B
#define SSTAGES 3
#define SSTAGE_B (2 * PLANE64)           // 36864
#define SSMEM (SSTAGES * SSTAGE_B)       // 110592

// p3 GEMM (out-proj, 2-MMA): 3 planes (Ah, Al, B), BK=64, 2 stages, 2 CTAs/SM
#define P3STAGES 2
#define P3STAGE_B (3 * PLANE64)          // 55296
#define P3SMEM (P3STAGES * P3STAGE_B)    // 110592

// transposed-epilogue staging pitch (halves)
#define PT 132

// ---- mainloop load macro (BK=64 single-plane, 256 threads) ----
#define ISSUE64(Ab, Bb, Kdim, it)                                              \
    do {                                                                       \
        const int s_ = (it) % SSTAGES;                                         \
        const int k0_ = (it) * BK64;                                           \
        const uint32_t stg_ = sbase + s_ * SSTAGE_B;                           \
        _Pragma("unroll")                                                      \
        for (int c_ = 0; c_ < 8; c_++) {                                       \
            const int id_ = tid + c_ * 256;                                    \
            const int seg_ = id_ >> 10;                                        \
            const int rid_ = id_ & 1023;                                       \
            const int row_ = rid_ >> 3, ch_ = rid_ & 7;                        \
            const __half* src_ = seg_ ? (Bb + (long long)(n0 + row_) * Kdim)   \
                                      : (Ab + (long long)(m0 + row_) * Kdim);  \
            cp16(stg_ + seg_ * PLANE64 + row_ * PITCH64 + ch_ * 16,            \
                 src_ + k0_ + ch_ * 8);                                        \
        }                                                                      \
    } while (0)

// ===========================================================================
// Fused Q/K/V projection (8 warps, 32x64 warp tiles)
// ===========================================================================
__global__ __launch_bounds__(THREADS, 2) void gemm_proj(
    const __half* __restrict__ Hm,
    const __half* __restrict__ Wqp, const __half* __restrict__ Wkp,
    const __half* __restrict__ Wvp,
    const float* __restrict__ bqp, const float* __restrict__ bkp,
    const float* __restrict__ bvp,
    __half* __restrict__ Qp, __half* __restrict__ Kp, __half* __restrict__ Vtp)
{
    cudaGridDependencySynchronize();   // PDL: wait for pack_w outputs
    extern __shared__ char smc[];
    const uint32_t sbase = smem_u32(smc);

    const int tid = threadIdx.x;
    const int wid = tid >> 5;
    const int lane = tid & 31;
    const int g = lane >> 2;
    const int t = lane & 3;
    const int z = blockIdx.z;

    const __half* Ab = Hm;
    const __half* Bb = (z == 0) ? Wqp : (z == 1) ? Wkp : Wvp;
    const float* bias = (z == 0) ? bqp : (z == 1) ? bkp : bvp;

    const int m0 = blockIdx.y * BM;
    const int n0 = blockIdx.x * BN;
    const int wm = (wid & 3) * 32;
    const int wn = (wid >> 2) * 64;
    const int K = DD, N = HH;

    float acc[2][8][4];
#pragma unroll
    for (int i = 0; i < 2; i++)
#pragma unroll
        for (int j = 0; j < 8; j++)
#pragma unroll
            for (int r = 0; r < 4; r++) acc[i][j][r] = 0.0f;

    const int niter = K / BK64;     // 4

#pragma unroll
    for (int it = 0; it < SSTAGES - 1; it++) { ISSUE64(Ab, Bb, K, it); CP_COMMIT(); }

    const int a_row = lane & 15;
    const int a_kc = (lane >> 4) * 8;
    const int b_n = ((lane >> 4) << 3) + (lane & 7);
    const int b_kc = ((lane >> 3) & 1) * 8;

    for (int it = 0; it < niter; it++) {
        CP_WAIT(SSTAGES - 2);
        __syncthreads();
        if (it + SSTAGES - 1 < niter) { ISSUE64(Ab, Bb, K, it + SSTAGES - 1); }
        CP_COMMIT();

        const uint32_t stg = sbase + (it % SSTAGES) * SSTAGE_B;
#pragma unroll
        for (int kk = 0; kk < BK64; kk += 16) {
            uint32_t Af[2][4];
#pragma unroll
            for (int i = 0; i < 2; i++)
                ldsm4(Af[i], stg + (uint32_t)(wm + i * 16 + a_row) * PITCH64
                               + (uint32_t)(kk + a_kc) * 2);
#pragma unroll
            for (int p = 0; p < 4; p++) {
                uint32_t Bf[4];
                ldsm4(Bf, stg + PLANE64 + (uint32_t)(wn + p * 16 + b_n) * PITCH64
                                        + (uint32_t)(kk + b_kc) * 2);
#pragma unroll
                for (int i = 0; i < 2; i++) {
                    mma_f16(acc[i][2 * p],     Af[i], &Bf[0]);
                    mma_f16(acc[i][2 * p + 1], Af[i], &Bf[2]);
                }
            }
        }
    }

    if (z < 2) {
        __half* C = (z == 0) ? Qp : Kp;
#pragma unroll
        for (int i = 0; i < 2; i++) {
            const int r0 = m0 + wm + i * 16 + g;
#pragma unroll
            for (int j = 0; j < 8; j++) {
                const int cc = n0 + wn + j * 8 + 2 * t;
                float b0 = bias[cc], b1 = bias[cc + 1];
                float x0 = fmaxf(acc[i][j][0] + b0, 0.f);
                float x1 = fmaxf(acc[i][j][1] + b1, 0.f);
                float x2 = fmaxf(acc[i][j][2] + b0, 0.f);
                float x3 = fmaxf(acc[i][j][3] + b1, 0.f);
                *(uint32_t*)(C + (long long)r0 * N + cc) =
                    packh2(__float2half_rn(x0), __float2half_rn(x1));
                *(uint32_t*)(C + (long long)(r0 + 8) * N + cc) =
                    packh2(__float2half_rn(x2), __float2half_rn(x3));
            }
        }
    } else {
        // V: stage tile in smem, write transposed vt[b][h][n]
        __syncthreads();
        __half* tile = (__half*)smc;
#pragma unroll
        for (int i = 0; i < 2; i++) {
            const int rl0 = wm + i * 16 + g;
#pragma unroll
            for (int j = 0; j < 8; j++) {
                const int cl = wn + j * 8 + 2 * t;
                float b0 = bias[n0 + cl], b1 = bias[n0 + cl + 1];
                tile[rl0 * PT + cl]           = __float2half_rn(fmaxf(acc[i][j][0] + b0, 0.f));
                tile[rl0 * PT + cl + 1]       = __float2half_rn(fmaxf(acc[i][j][1] + b1, 0.f));
                tile[(rl0 + 8) * PT + cl]     = __float2half_rn(fmaxf(acc[i][j][2] + b0, 0.f));
                tile[(rl0 + 8) * PT + cl + 1] = __float2half_rn(fmaxf(acc[i][j][3] + b1, 0.f));
            }
        }
        __syncthreads();
        const int b = m0 >> 10;
        const int nloc = m0 & 1023;
        __half* vtb = Vtp + (long long)b * HH * NN + nloc;
        const int g2 = tid >> 7;
        const int l128 = tid & 127;
#pragma unroll
        for (int jc = 0; jc < 64; jc++) {
            const int c = g2 * 64 + jc;
            vtb[(long long)(n0 + c) * NN + l128] = tile[l128 * PT + c];
        }
    }
}

// ===========================================================================
// S GEMM with online-exp epilogue (8 warps, 32x64)
// ===========================================================================
__global__ __launch_bounds__(THREADS, 2) void gemm_qk(
    const __half* __restrict__ Q, const __half* __restrict__ Kx,
    __half* __restrict__ E, float* __restrict__ mloc, float* __restrict__ rsum)
{
    cudaGridDependencySynchronize();   // PDL: wait for proj outputs
    extern __shared__ char smc[];
    __shared__ float sred[2][128];
    const uint32_t sbase = smem_u32(smc);

    const int tid = threadIdx.x;
    const int wid = tid >> 5;
    const int lane = tid & 31;
    const int g = lane >> 2;
    const int t = lane & 3;
    const int bz = blockIdx.z;

    const __half* Ab = Q + ((long long)bz * NN * HH);
    const __half* Bb = Kx + ((long long)bz * NN * HH);
    const int m0 = blockIdx.y * BM;
    const int n0 = blockIdx.x * BN;
    const int wm = (wid & 3) * 32;
    const int wn = (wid >> 2) * 64;
    const int K = HH;

    float acc[2][8][4];
#pragma unroll
    for (int i = 0; i < 2; i++)
#pragma unroll
        for (int j = 0; j < 8; j++)
#pragma unroll
            for (int r = 0; r < 4; r++) acc[i][j][r] = 0.0f;

    const int niter = K / BK64;   // 8

#pragma unroll
    for (int it = 0; it < SSTAGES - 1; it++) { ISSUE64(Ab, Bb, K, it); CP_COMMIT(); }

    const int a_row = lane & 15;
    const int a_kc = (lane >> 4) * 8;
    const int b_n = ((lane >> 4) << 3) + (lane & 7);
    const int b_kc = ((lane >> 3) & 1) * 8;

    for (int it = 0; it < niter; it++) {
        CP_WAIT(SSTAGES - 2);
        __syncthreads();
        if (it + SSTAGES - 1 < niter) { ISSUE64(Ab, Bb, K, it + SSTAGES - 1); }
        CP_COMMIT();

        const uint32_t stg = sbase + (it % SSTAGES) * SSTAGE_B;
#pragma unroll
        for (int kk = 0; kk < BK64; kk += 16) {
            uint32_t Af[2][4];
#pragma unroll
            for (int i = 0; i < 2; i++)
                ldsm4(Af[i], stg + (uint32_t)(wm + i * 16 + a_row) * PITCH64
                               + (uint32_t)(kk + a_kc) * 2);
#pragma unroll
            for (int p = 0; p < 4; p++) {
                uint32_t Bf[4];
                ldsm4(Bf, stg + PLANE64 + (uint32_t)(wn + p * 16 + b_n) * PITCH64
                                        + (uint32_t)(kk + b_kc) * 2);
#pragma unroll
                for (int i = 0; i < 2; i++) {
                    mma_f16(acc[i][2 * p],     Af[i], &Bf[0]);
                    mma_f16(acc[i][2 * p + 1], Af[i], &Bf[2]);
                }
            }
        }
    }

    // ---- online-exp epilogue (bit-exact order) ----
    const int R0 = wm + g, R1 = wm + g + 8, R2 = wm + 16 + g, R3 = wm + 24 + g;
    const int half = wid >> 2;

    float rm[4] = {-1e30f, -1e30f, -1e30f, -1e30f};
#pragma unroll
    for (int j = 0; j < 8; j++) {
        rm[0] = fmaxf(rm[0], fmaxf(acc[0][j][0], acc[0][j][1]));
        rm[1] = fmaxf(rm[1], fmaxf(acc[0][j][2], acc[0][j][3]));
        rm[2] = fmaxf(rm[2], fmaxf(acc[1][j][0], acc[1][j][1]));
        rm[3] = fmaxf(rm[3], fmaxf(acc[1][j][2], acc[1][j][3]));
    }
#pragma unroll
    for (int o = 1; o <= 2; o <<= 1)
#pragma unroll
        for (int k = 0; k < 4; k++)
            rm[k] = fmaxf(rm[k], __shfl_xor_sync(0xffffffffu, rm[k], o));

    __syncthreads();
    if (t == 0) {
        sred[half][R0] = rm[0]; sred[half][R1] = rm[1];
        sred[half][R2] = rm[2]; sred[half][R3] = rm[3];
    }
    __syncthreads();
    float gm[4];
    gm[0] = fmaxf(sred[0][R0], sred[1][R0]);
    gm[1] = fmaxf(sred[0][R1], sred[1][R1]);
    gm[2] = fmaxf(sred[0][R2], sred[1][R2]);
    gm[3] = fmaxf(sred[0][R3], sred[1][R3]);
    __syncthreads();

    float rs[4] = {0.f, 0.f, 0.f, 0.f};
#pragma unroll
    for (int j = 0; j < 8; j++) {
        acc[0][j][0] = __expf(acc[0][j][0] - gm[0]);
        acc[0][j][1] = __expf(acc[0][j][1] - gm[0]);
        rs[0] += acc[0][j][0] + acc[0][j][1];
        acc[0][j][2] = __expf(acc[0][j][2] - gm[1]);
        acc[0][j][3] = __expf(acc[0][j][3] - gm[1]);
        rs[1] += acc[0][j][2] + acc[0][j][3];
        acc[1][j][0] = __expf(acc[1][j][0] - gm[2]);
        acc[1][j][1] = __expf(acc[1][j][1] - gm[2]);
        rs[2] += acc[1][j][0] + acc[1][j][1];
        acc[1][j][2] = __expf(acc[1][j][2] - gm[3]);
        acc[1][j][3] = __expf(acc[1][j][3] - gm[3]);
        rs[3] += acc[1][j][2] + acc[1][j][3];
    }
#pragma unroll
    for (int o = 1; o <= 2; o <<= 1)
#pragma unroll
        for (int k = 0; k < 4; k++)
            rs[k] += __shfl_xor_sync(0xffffffffu, rs[k], o);

    if (t == 0 && half == 0) {
        sred[0][R0] = rs[0]; sred[0][R1] = rs[1];
        sred[0][R2] = rs[2]; sred[0][R3] = rs[3];
    }
    __syncthreads();
    if (t == 0 && half == 1) {
        atomicAdd(&sred[0][R0], rs[0]); atomicAdd(&sred[0][R1], rs[1]);
        atomicAdd(&sred[0][R2], rs[2]); atomicAdd(&sred[0][R3], rs[3]);
    }
    __syncthreads();

    if (t == 0 && half == 0) {
        const long long sb = ((long long)(bz * NTILE + blockIdx.x) << 10) + m0;
        mloc[sb + R0] = gm[0]; rsum[sb + R0] = sred[0][R0];
        mloc[sb + R1] = gm[1]; rsum[sb + R1] = sred[0][R1];
        mloc[sb + R2] = gm[2]; rsum[sb + R2] = sred[0][R2];
        mloc[sb + R3] = gm[3]; rsum[sb + R3] = sred[0][R3];
    }

    __half* Eb = E + ((long long)bz << 20);
#pragma unroll
    for (int i = 0; i < 2; i++) {
        const int r0 = m0 + wm + i * 16 + g;
#pragma unroll
        for (int j = 0; j < 8; j++) {
            const int cc = n0 + wn + j * 8 + 2 * t;
            *(uint32_t*)(Eb + (long long)r0 * NN + cc) =
                packh2(__float2half_rn(acc[i][j][0]), __float2half_rn(acc[i][j][1]));
            *(uint32_t*)(Eb + (long long)(r0 + 8) * NN + cc) =
                packh2(__float2half_rn(acc[i][j][2]), __float2half_rn(acc[i][j][3]));
        }
    }
}

// ===========================================================================
// O GEMM: O = (diag-scaled E) * Vt^T -> half-pair, stats inlined
// ===========================================================================
__global__ __launch_bounds__(THREADS, 2) void gemm_pv(
    const __half* __restrict__ E, const __half* __restrict__ Vt,
    const float* __restrict__ mloc, const float* __restrict__ rsum,
    __half* __restrict__ O2, long long sPC)
{
    cudaGridDependencySynchronize();   // PDL: wait for qk outputs
    extern __shared__ char smc[];
    __shared__ float sscl[NTILE][128];
    const uint32_t sbase = smem_u32(smc);

    const int tid = threadIdx.x;
    const int wid = tid >> 5;
    const int lane = tid & 31;
    const int g = lane >> 2;
    const int t = lane & 3;
    const int bz = blockIdx.z;

    const __half* Ab = E + ((long long)bz << 20);
    const __half* Bb = Vt + ((long long)bz * HH * NN);
    const int m0 = blockIdx.y * BM;
    const int n0 = blockIdx.x * BN;
    const int wm = (wid & 3) * 32;
    const int wn = (wid >> 2) * 64;
    const int N = HH, K = NN;

    // inline stats (identical op order)
    if (tid < 128) {
        const int r = m0 + tid;
        float m[NTILE], s[NTILE];
        float M = -1e30f;
#pragma unroll
        for (int tt = 0; tt < NTILE; tt++) {
            const long long p = ((long long)(bz * NTILE + tt) << 10) + r;
            m[tt] = mloc[p]; s[tt] = rsum[p];
            M = fmaxf(M, m[tt]);
        }
        float denom = 0.f;
#pragma unroll
        for (int tt = 0; tt < NTILE; tt++) {
            m[tt] = __expf(m[tt] - M);
            denom += s[tt] * m[tt];
        }
        const float inv = 1.0f / denom;
#pragma unroll
        for (int tt = 0; tt < NTILE; tt++)
            sscl[tt][tid] = m[tt] * inv;
    }

    float acc[2][8][4];
#pragma unroll
    for (int i = 0; i < 2; i++)
#pragma unroll
        for (int j = 0; j < 8; j++)
#pragma unroll
            for (int r = 0; r < 4; r++) acc[i][j][r] = 0.0f;

    const int niter = K / BK64;   // 16

#pragma unroll
    for (int it = 0; it < SSTAGES - 1; it++) { ISSUE64(Ab, Bb, K, it); CP_COMMIT(); }
    __syncthreads();   // sscl ready

    const int a_row = lane & 15;
    const int a_kc = (lane >> 4) * 8;
    const int b_n = ((lane >> 4) << 3) + (lane & 7);
    const int b_kc = ((lane >> 3) & 1) * 8;

    const int R0 = wm + g, R1 = wm + g + 8, R2 = wm + 16 + g, R3 = wm + 24 + g;
    __half2 hs[4];

    for (int it = 0; it < niter; it++) {
        CP_WAIT(SSTAGES - 2);
        __syncthreads();
        if (it + SSTAGES - 1 < niter) { ISSUE64(Ab, Bb, K, it + SSTAGES - 1); }
        CP_COMMIT();

        if ((it & 1) == 0) {
            const int tt = it >> 1;
            hs[0] = __float2half2_rn(sscl[tt][R0]);
            hs[1] = __float2half2_rn(sscl[tt][R1]);
            hs[2] = __float2half2_rn(sscl[tt][R2]);
            hs[3] = __float2half2_rn(sscl[tt][R3]);
        }

        const uint32_t stg = sbase + (it % SSTAGES) * SSTAGE_B;
#pragma unroll
        for (int kk = 0; kk < BK64; kk += 16) {
            uint32_t Af[2][4];
#pragma unroll
            for (int i = 0; i < 2; i++) {
                ldsm4(Af[i], stg + (uint32_t)(wm + i * 16 + a_row) * PITCH64
                               + (uint32_t)(kk + a_kc) * 2);
                Af[i][0] = mulh2(Af[i][0], hs[2 * i]);
                Af[i][1] = mulh2(Af[i][1], hs[2 * i + 1]);
                Af[i][2] = mulh2(Af[i][2], hs[2 * i]);
                Af[i][3] = mulh2(Af[i][3], hs[2 * i + 1]);
            }
#pragma unroll
            for (int p = 0; p < 4; p++) {
                uint32_t Bf[4];
                ldsm4(Bf, stg + PLANE64 + (uint32_t)(wn + p * 16 + b_n) * PITCH64
                                        + (uint32_t)(kk + b_kc) * 2);
#pragma unroll
                for (int i = 0; i < 2; i++) {
                    mma_f16(acc[i][2 * p],     Af[i], &Bf[0]);
                    mma_f16(acc[i][2 * p + 1], Af[i], &Bf[2]);
                }
            }
        }
    }

    __half* Ch = O2 + (long long)bz * NN * HH;
    __half* Cl = Ch + sPC;
#pragma unroll
    for (int i = 0; i < 2; i++) {
        const int r0 = m0 + wm + i * 16 + g;
#pragma unroll
        for (int j = 0; j < 8; j++) {
            const int cc = n0 + wn + j * 8 + 2 * t;
            __half h0, l0, h1, l1, h2, l2, h3, l3;
            h_split(acc[i][j][0], h0, l0); h_split(acc[i][j][1], h1, l1);
            h_split(acc[i][j][2], h2, l2); h_split(acc[i][j][3], h3, l3);
            *(uint32_t*)(Ch + (long long)r0 * N + cc)       = packh2(h0, h1);
            *(uint32_t*)(Cl + (long long)r0 * N + cc)       = packh2(l0, l1);
            *(uint32_t*)(Ch + (long long)(r0 + 8) * N + cc) = packh2(h2, h3);
            *(uint32_t*)(Cl + (long long)(r0 + 8) * N + cc) = packh2(l2, l3);
        }
    }
}

// ===========================================================================
// Out-proj GEMM (2 MMAs): out = relu((o_hi + o_lo) Wo_hi^T + bo), fp32 out.
// ===========================================================================
__global__ __launch_bounds__(THREADS, 2) void gemm_p3(
    const __half* __restrict__ A, const __half* __restrict__ B,
    const float* __restrict__ bias, float* __restrict__ C,
    int M, int N, int K, long long sPA)
{
    cudaGridDependencySynchronize();   // PDL: wait for pv outputs
    extern __shared__ char smc[];
    const uint32_t sbase = smem_u32(smc);

    const int tid = threadIdx.x;
    const int wid = tid >> 5;
    const int lane = tid & 31;
    const int g = lane >> 2;
    const int t = lane & 3;

    const __half* Ah = A;
    const __half* Al = A + sPA;
    const int m0 = blockIdx.y * BM;
    const int n0 = blockIdx.x * BN;
    const int wm = (wid & 3) * 32;
    const int wn = (wid >> 2) * 64;

    float acc[2][8][4];
#pragma unroll
    for (int i = 0; i < 2; i++)
#pragma unroll
        for (int j = 0; j < 8; j++)
#pragma unroll
            for (int r = 0; r < 4; r++) acc[i][j][r] = 0.0f;

    const int niter = K / BK64;   // 8

    auto issue_loads = [&](int it) {
        const int s = it % P3STAGES;
        const int k0 = it * BK64;
        const uint32_t stg = sbase + s * P3STAGE_B;
#pragma unroll
        for (int c = 0; c < 12; c++) {
            const int id = tid + c * 256;
            const int seg = id >> 10;
            const int rid = id & 1023;
            const int row = rid >> 3, ch = rid & 7;
            const __half* src = (seg == 0) ? (Ah + (long long)(m0 + row) * K)
                              : (seg == 1) ? (Al + (long long)(m0 + row) * K)
                                           : (B  + (long long)(n0 + row) * K);
            cp16(stg + seg * PLANE64 + row * PITCH64 + ch * 16,
                 src + k0 + ch * 8);
        }
    };

#pragma unroll
    for (int it = 0; it < P3STAGES - 1; it++) { issue_loads(it); CP_COMMIT(); }

    const int a_row = lane & 15;
    const int a_kc = (lane >> 4) * 8;
    const int b_n = ((lane >> 4) << 3) + (lane & 7);
    const int b_kc = ((lane >> 3) & 1) * 8;

    for (int it = 0; it < niter; it++) {
        CP_WAIT(P3STAGES - 2);
        __syncthreads();
        if (it + P3STAGES - 1 < niter) issue_loads(it + P3STAGES - 1);
        CP_COMMIT();

        const uint32_t stg = sbase + (it % P3STAGES) * P3STAGE_B;
#pragma unroll
        for (int kk = 0; kk < BK64; kk += 16) {
            uint32_t Afh[2][4], Afl[2][4];
#pragma unroll
            for (int i = 0; i < 2; i++) {
                const uint32_t ao = (uint32_t)(wm + i * 16 + a_row) * PITCH64
                                  + (uint32_t)(kk + a_kc) * 2;
                ldsm4(Afh[i], stg + ao);
                ldsm4(Afl[i], stg + PLANE64 + ao);
            }
#pragma unroll
            for (int p = 0; p < 4; p++) {
                uint32_t Bf[4];
                ldsm4(Bf, stg + 2 * PLANE64
                         + (uint32_t)(wn + p * 16 + b_n) * PITCH64
                         + (uint32_t)(kk + b_kc) * 2);
#pragma unroll
                for (int i = 0; i < 2; i++) {
                    mma_f16(acc[i][2 * p],     Afh[i], &Bf[0]);
                    mma_f16(acc[i][2 * p],     Afl[i], &Bf[0]);
                    mma_f16(acc[i][2 * p + 1], Afh[i], &Bf[2]);
                    mma_f16(acc[i][2 * p + 1], Afl[i], &Bf[2]);
                }
            }
        }
    }

#pragma unroll
    for (int i = 0; i < 2; i++) {
        const int r0 = m0 + wm + i * 16 + g;
#pragma unroll
        for (int j = 0; j < 8; j++) {
            const int cc = n0 + wn + j * 8 + 2 * t;
            float b0 = bias[cc], b1 = bias[cc + 1];
            *(float2*)(C + (long long)r0 * N + cc) =
                make_float2(fmaxf(acc[i][j][0] + b0, 0.f), fmaxf(acc[i][j][1] + b1, 0.f));
            *(float2*)(C + (long long)(r0 + 8) * N + cc) =
                make_float2(fmaxf(acc[i][j][2] + b0, 0.f), fmaxf(acc[i][j][3] + b1, 0.f));
        }
    }
}

// ---------------------------------------------------------------------------
// fused pack: h + all 4 weights -> fp16 (single plane each)
// ---------------------------------------------------------------------------
#define PK_H (HB_ELEMS / 4)
#define PK_W (W1_ELEMS / 4)
__global__ __launch_bounds__(256) void pack_all(
    const float* __restrict__ h, const float* __restrict__ Wq,
    const float* __restrict__ Wk, const float* __restrict__ Wv,
    const float* __restrict__ Wo,
    __half* __restrict__ h16, __half* __restrict__ wq16,
    __half* __restrict__ wk16, __half* __restrict__ wv16,
    __half* __restrict__ wo16)
{
    const int total = PK_H + 4 * PK_W;
    for (int i = blockIdx.x * blockDim.x + threadIdx.x; i < total;
         i += gridDim.x * blockDim.x) {
        const float* src; __half* dst; int idx;
        if (i < PK_H) { src = h; dst = h16; idx = i; }
        else {
            int r = i - PK_H;
            int seg = r / PK_W; idx = r % PK_W;
            src = (seg == 0) ? Wq : (seg == 1) ? Wk : (seg == 2) ? Wv : Wo;
            dst = (seg == 0) ? wq16 : (seg == 1) ? wk16 : (seg == 2) ? wv16 : wo16;
        }
        float4 v = ((const float4*)src)[idx];
        ((uint2*)dst)[idx] = make_uint2(
            packh2(__float2half_rn(v.x), __float2half_rn(v.y)),
            packh2(__float2half_rn(v.z), __float2half_rn(v.w)));
    }
}

// ---------------------------------------------------------------------------
// PDL launch helper
// ---------------------------------------------------------------------------
template <typename... Args>
static void launch_pdl(void (*kfn)(Args...), dim3 grid, int smem, Args... args)
{
    cudaLaunchConfig_t cfg = {};
    cfg.gridDim = grid;
    cfg.blockDim = dim3(THREADS, 1, 1);
    cfg.dynamicSmemBytes = (size_t)smem;
    cfg.stream = 0;
    cudaLaunchAttribute attr[1];
    attr[0].id = cudaLaunchAttributeProgrammaticStreamSerialization;
    attr[0].val.programmaticStreamSerializationAllowed = 1;
    cfg.attrs = attr;
    cfg.numAttrs = 1;
    cudaLaunchKernelEx(&cfg, kfn, args...);
}

// ---------------------------------------------------------------------------
// kernel_launch — inputs: h, Wv, bv, Wk, bk, Wq, bq, Wo, bo
// ---------------------------------------------------------------------------
extern "C" void kernel_launch(void* const* d_in, const int* in_sizes, int n_in,
                              void* d_out, int out_size)
{
    const float* h  = (const float*)d_in[0];
    const float* Wv = (const float*)d_in[1];
    const float* bv = (const float*)d_in[2];
    const float* Wk = (const float*)d_in[3];
    const float* bk = (const float*)d_in[4];
    const float* Wq = (const float*)d_in[5];
    const float* bq = (const float*)d_in[6];
    const float* Wo = (const float*)d_in[7];
    const float* bo = (const float*)d_in[8];
    float* out = (float*)d_out;

    __half *h16, *wq16, *wk16, *wv16, *wo16, *q, *k, *vt, *e, *o2;
    float *mloc, *rsum;
    cudaGetSymbolAddress((void**)&h16,  g_h16);
    cudaGetSymbolAddress((void**)&wq16, g_wq16);
    cudaGetSymbolAddress((void**)&wk16, g_wk16);
    cudaGetSymbolAddress((void**)&wv16, g_wv16);
    cudaGetSymbolAddress((void**)&wo16, g_wo16);
    cudaGetSymbolAddress((void**)&q,    g_q);
    cudaGetSymbolAddress((void**)&k,    g_k);
    cudaGetSymbolAddress((void**)&vt,   g_vt);
    cudaGetSymbolAddress((void**)&e,    g_e);
    cudaGetSymbolAddress((void**)&mloc, g_mloc);
    cudaGetSymbolAddress((void**)&rsum, g_rsum);
    cudaGetSymbolAddress((void**)&o2,   g_o2);

    cudaFuncSetAttribute(gemm_proj, cudaFuncAttributeMaxDynamicSharedMemorySize, SSMEM);
    cudaFuncSetAttribute(gemm_qk,   cudaFuncAttributeMaxDynamicSharedMemorySize, SSMEM);
    cudaFuncSetAttribute(gemm_pv,   cudaFuncAttributeMaxDynamicSharedMemorySize, SSMEM);
    cudaFuncSetAttribute(gemm_p3,   cudaFuncAttributeMaxDynamicSharedMemorySize, P3SMEM);

    const int M = BB * NN;   // 32768

    // 1. fused pack (normal launch)
    pack_all<<<2048, 256>>>(h, Wq, Wk, Wv, Wo, h16, wq16, wk16, wv16, wo16);

    // 2. fused Q/K/V projections; z==2 writes vt directly (PDL)
    launch_pdl(gemm_proj, dim3(HH / BN, M / BM, 3), SSMEM,
               (const __half*)h16, (const __half*)wq16, (const __half*)wk16,
               (const __half*)wv16, bq, bk, bv,
               (__half*)q, (__half*)k, (__half*)vt);

    // 3. S GEMM + online exp -> e fp16 + per-tile stats (PDL)
    launch_pdl(gemm_qk, dim3(NN / BN, NN / BM, BB), SSMEM,
               (const __half*)q, (const __half*)k,
               (__half*)e, (float*)mloc, (float*)rsum);

    // 4. O = scaled-E * Vt^T -> fp16 pair, stats inlined (PDL)
    launch_pdl(gemm_pv, dim3(HH / BN, NN / BM, BB), SSMEM,
               (const __half*)e, (const __half*)vt,
               (const float*)mloc, (const float*)rsum,
               (__half*)o2, (long long)QKV_ELEMS);

    // 5. out = relu(O Wo^T + bo) -> fp32, 2-MMA pair-A GEMM (PDL)
    launch_pdl(gemm_p3, dim3(DD / BN, M / BM, 1), P3SMEM,
               (const __half*)o2, (const __half*)wo16, bo, out,
               M, DD, HH, (long long)QKV_ELEMS);
}

// round 16
// speedup vs baseline: 1.1452x; 1.0832x over previous
#include <cuda_runtime.h>
#include <cuda_fp16.h>
#include <cstdint>

// Problem dims
#define BB 32
#define NN 1024
#define DD 256
#define HH 512
#define HB_ELEMS (BB * NN * DD)
#define QKV_ELEMS (BB * NN * HH)
#define S_ELEMS ((long long)BB * NN * NN)
#define W1_ELEMS (HH * DD)
#define NTILE 8

// ---------------- scratch ----------------
__device__ __half g_h16[HB_ELEMS];
__device__ __half g_wq16[W1_ELEMS], g_wk16[W1_ELEMS], g_wv16[W1_ELEMS];
__device__ __half g_wo16[W1_ELEMS];
__device__ __half g_q[QKV_ELEMS], g_k[QKV_ELEMS];
__device__ __half g_vt[QKV_ELEMS];              // [b][h][n]
__device__ __half g_e[S_ELEMS];
__device__ float  g_mloc[BB * NTILE * NN];
__device__ float  g_rsum[BB * NTILE * NN];
__device__ __half g_o16[QKV_ELEMS];             // O single fp16 plane

// ---------------- helpers ----------------
__device__ __forceinline__ uint32_t packh2(__half a, __half b) {
    __half2 t = __halves2half2(a, b);
    return *reinterpret_cast<uint32_t*>(&t);
}
__device__ __forceinline__ uint32_t mulh2(uint32_t a, __half2 s) {
    __half2 x = *reinterpret_cast<__half2*>(&a);
    x = __hmul2(x, s);
    return *reinterpret_cast<uint32_t*>(&x);
}
__device__ __forceinline__ uint32_t smem_u32(const void* p) {
    uint32_t a;
    asm("{ .reg .u64 t; cvta.to.shared.u64 t, %1; cvt.u32.u64 %0, t; }" : "=r"(a) : "l"(p));
    return a;
}
__device__ __forceinline__ void cp16(uint32_t dst, const void* src) {
    asm volatile("cp.async.cg.shared.global [%0], [%1], 16;" :: "r"(dst), "l"(src));
}
#define CP_COMMIT() asm volatile("cp.async.commit_group;" ::: "memory")
#define CP_WAIT(n)  asm volatile("cp.async.wait_group %0;" :: "n"(n) : "memory")

__device__ __forceinline__ void ldsm4(uint32_t* r, uint32_t addr) {
    asm volatile("ldmatrix.sync.aligned.m8n8.x4.shared.b16 {%0,%1,%2,%3}, [%4];"
        : "=r"(r[0]), "=r"(r[1]), "=r"(r[2]), "=r"(r[3]) : "r"(addr));
}
__device__ __forceinline__ void mma_f16(float* d, const uint32_t* a, const uint32_t* b) {
    asm volatile(
        "mma.sync.aligned.m16n8k16.row.col.f32.f16.f16.f32 "
        "{%0,%1,%2,%3}, {%4,%5,%6,%7}, {%8,%9}, {%0,%1,%2,%3};"
        : "+f"(d[0]), "+f"(d[1]), "+f"(d[2]), "+f"(d[3])
        : "r"(a[0]), "r"(a[1]), "r"(a[2]), "r"(a[3]), "r"(b[0]), "r"(b[1]));
}

// ---------------- tile config ----------------
#define BM 128
#define BN 128
#define THREADS 256

// single-plane GEMMs: BK=64, pitch 144 B, 3 stages, 2 CTAs/SM
#define BK64 64
#define PITCH64 144
#define PLANE64 (128 * PITCH64)          // 18432 B
#define SSTAGES 3
#define SSTAGE_B (2 * PLANE64)           // 36864
#define SSMEM (SSTAGES * SSTAGE_B)       // 110592

// transposed-epilogue staging pitch (halves)
#define PT 132

// ---- mainloop load macro (BK=64 single-plane, 256 threads) ----
#define ISSUE64(Ab, Bb, Kdim, it)                                              \
    do {                                                                       \
        const int s_ = (it) % SSTAGES;                                         \
        const int k0_ = (it) * BK64;                                           \
        const uint32_t stg_ = sbase + s_ * SSTAGE_B;                           \
        _Pragma("unroll")                                                      \
        for (int c_ = 0; c_ < 8; c_++) {                                       \
            const int id_ = tid + c_ * 256;                                    \
            const int seg_ = id_ >> 10;                                        \
            const int rid_ = id_ & 1023;                                       \
            const int row_ = rid_ >> 3, ch_ = rid_ & 7;                        \
            const __half* src_ = seg_ ? (Bb + (long long)(n0 + row_) * Kdim)   \
                                      : (Ab + (long long)(m0 + row_) * Kdim);  \
            cp16(stg_ + seg_ * PLANE64 + row_ * PITCH64 + ch_ * 16,            \
                 src_ + k0_ + ch_ * 8);                                        \
        }                                                                      \
    } while (0)

// ===========================================================================
// Fused Q/K/V projection (8 warps, 32x64 warp tiles)
// ===========================================================================
__global__ __launch_bounds__(THREADS, 2) void gemm_proj(
    const __half* __restrict__ Hm,
    const __half* __restrict__ Wqp, const __half* __restrict__ Wkp,
    const __half* __restrict__ Wvp,
    const float* __restrict__ bqp, const float* __restrict__ bkp,
    const float* __restrict__ bvp,
    __half* __restrict__ Qp, __half* __restrict__ Kp, __half* __restrict__ Vtp)
{
    cudaGridDependencySynchronize();   // PDL
    extern __shared__ char smc[];
    const uint32_t sbase = smem_u32(smc);

    const int tid = threadIdx.x;
    const int wid = tid >> 5;
    const int lane = tid & 31;
    const int g = lane >> 2;
    const int t = lane & 3;
    const int z = blockIdx.z;

    const __half* Ab = Hm;
    const __half* Bb = (z == 0) ? Wqp : (z == 1) ? Wkp : Wvp;
    const float* bias = (z == 0) ? bqp : (z == 1) ? bkp : bvp;

    const int m0 = blockIdx.y * BM;
    const int n0 = blockIdx.x * BN;
    const int wm = (wid & 3) * 32;
    const int wn = (wid >> 2) * 64;
    const int K = DD, N = HH;

    float acc[2][8][4];
#pragma unroll
    for (int i = 0; i < 2; i++)
#pragma unroll
        for (int j = 0; j < 8; j++)
#pragma unroll
            for (int r = 0; r < 4; r++) acc[i][j][r] = 0.0f;

    const int niter = K / BK64;     // 4

#pragma unroll
    for (int it = 0; it < SSTAGES - 1; it++) { ISSUE64(Ab, Bb, K, it); CP_COMMIT(); }

    const int a_row = lane & 15;
    const int a_kc = (lane >> 4) * 8;
    const int b_n = ((lane >> 4) << 3) + (lane & 7);
    const int b_kc = ((lane >> 3) & 1) * 8;

    for (int it = 0; it < niter; it++) {
        CP_WAIT(SSTAGES - 2);
        __syncthreads();
        if (it + SSTAGES - 1 < niter) { ISSUE64(Ab, Bb, K, it + SSTAGES - 1); }
        CP_COMMIT();

        const uint32_t stg = sbase + (it % SSTAGES) * SSTAGE_B;
#pragma unroll
        for (int kk = 0; kk < BK64; kk += 16) {
            uint32_t Af[2][4];
#pragma unroll
            for (int i = 0; i < 2; i++)
                ldsm4(Af[i], stg + (uint32_t)(wm + i * 16 + a_row) * PITCH64
                               + (uint32_t)(kk + a_kc) * 2);
#pragma unroll
            for (int p = 0; p < 4; p++) {
                uint32_t Bf[4];
                ldsm4(Bf, stg + PLANE64 + (uint32_t)(wn + p * 16 + b_n) * PITCH64
                                        + (uint32_t)(kk + b_kc) * 2);
#pragma unroll
                for (int i = 0; i < 2; i++) {
                    mma_f16(acc[i][2 * p],     Af[i], &Bf[0]);
                    mma_f16(acc[i][2 * p + 1], Af[i], &Bf[2]);
                }
            }
        }
    }

    if (z < 2) {
        __half* C = (z == 0) ? Qp : Kp;
#pragma unroll
        for (int i = 0; i < 2; i++) {
            const int r0 = m0 + wm + i * 16 + g;
#pragma unroll
            for (int j = 0; j < 8; j++) {
                const int cc = n0 + wn + j * 8 + 2 * t;
                float b0 = bias[cc], b1 = bias[cc + 1];
                float x0 = fmaxf(acc[i][j][0] + b0, 0.f);
                float x1 = fmaxf(acc[i][j][1] + b1, 0.f);
                float x2 = fmaxf(acc[i][j][2] + b0, 0.f);
                float x3 = fmaxf(acc[i][j][3] + b1, 0.f);
                *(uint32_t*)(C + (long long)r0 * N + cc) =
                    packh2(__float2half_rn(x0), __float2half_rn(x1));
                *(uint32_t*)(C + (long long)(r0 + 8) * N + cc) =
                    packh2(__float2half_rn(x2), __float2half_rn(x3));
            }
        }
    } else {
        // V: stage tile in smem, write transposed vt[b][h][n]
        __syncthreads();
        __half* tile = (__half*)smc;
#pragma unroll
        for (int i = 0; i < 2; i++) {
            const int rl0 = wm + i * 16 + g;
#pragma unroll
            for (int j = 0; j < 8; j++) {
                const int cl = wn + j * 8 + 2 * t;
                float b0 = bias[n0 + cl], b1 = bias[n0 + cl + 1];
                tile[rl0 * PT + cl]           = __float2half_rn(fmaxf(acc[i][j][0] + b0, 0.f));
                tile[rl0 * PT + cl + 1]       = __float2half_rn(fmaxf(acc[i][j][1] + b1, 0.f));
                tile[(rl0 + 8) * PT + cl]     = __float2half_rn(fmaxf(acc[i][j][2] + b0, 0.f));
                tile[(rl0 + 8) * PT + cl + 1] = __float2half_rn(fmaxf(acc[i][j][3] + b1, 0.f));
            }
        }
        __syncthreads();
        const int b = m0 >> 10;
        const int nloc = m0 & 1023;
        __half* vtb = Vtp + (long long)b * HH * NN + nloc;
        const int g2 = tid >> 7;
        const int l128 = tid & 127;
#pragma unroll
        for (int jc = 0; jc < 64; jc++) {
            const int c = g2 * 64 + jc;
            vtb[(long long)(n0 + c) * NN + l128] = tile[l128 * PT + c];
        }
    }
}

// ===========================================================================
// S GEMM with online-exp epilogue (8 warps, 32x64)
// ===========================================================================
__global__ __launch_bounds__(THREADS, 2) void gemm_qk(
    const __half* __restrict__ Q, const __half* __restrict__ Kx,
    __half* __restrict__ E, float* __restrict__ mloc, float* __restrict__ rsum)
{
    cudaGridDependencySynchronize();   // PDL
    extern __shared__ char smc[];
    __shared__ float sred[2][128];
    const uint32_t sbase = smem_u32(smc);

    const int tid = threadIdx.x;
    const int wid = tid >> 5;
    const int lane = tid & 31;
    const int g = lane >> 2;
    const int t = lane & 3;
    const int bz = blockIdx.z;

    const __half* Ab = Q + ((long long)bz * NN * HH);
    const __half* Bb = Kx + ((long long)bz * NN * HH);
    const int m0 = blockIdx.y * BM;
    const int n0 = blockIdx.x * BN;
    const int wm = (wid & 3) * 32;
    const int wn = (wid >> 2) * 64;
    const int K = HH;

    float acc[2][8][4];
#pragma unroll
    for (int i = 0; i < 2; i++)
#pragma unroll
        for (int j = 0; j < 8; j++)
#pragma unroll
            for (int r = 0; r < 4; r++) acc[i][j][r] = 0.0f;

    const int niter = K / BK64;   // 8

#pragma unroll
    for (int it = 0; it < SSTAGES - 1; it++) { ISSUE64(Ab, Bb, K, it); CP_COMMIT(); }

    const int a_row = lane & 15;
    const int a_kc = (lane >> 4) * 8;
    const int b_n = ((lane >> 4) << 3) + (lane & 7);
    const int b_kc = ((lane >> 3) & 1) * 8;

    for (int it = 0; it < niter; it++) {
        CP_WAIT(SSTAGES - 2);
        __syncthreads();
        if (it + SSTAGES - 1 < niter) { ISSUE64(Ab, Bb, K, it + SSTAGES - 1); }
        CP_COMMIT();

        const uint32_t stg = sbase + (it % SSTAGES) * SSTAGE_B;
#pragma unroll
        for (int kk = 0; kk < BK64; kk += 16) {
            uint32_t Af[2][4];
#pragma unroll
            for (int i = 0; i < 2; i++)
                ldsm4(Af[i], stg + (uint32_t)(wm + i * 16 + a_row) * PITCH64
                               + (uint32_t)(kk + a_kc) * 2);
#pragma unroll
            for (int p = 0; p < 4; p++) {
                uint32_t Bf[4];
                ldsm4(Bf, stg + PLANE64 + (uint32_t)(wn + p * 16 + b_n) * PITCH64
                                        + (uint32_t)(kk + b_kc) * 2);
#pragma unroll
                for (int i = 0; i < 2; i++) {
                    mma_f16(acc[i][2 * p],     Af[i], &Bf[0]);
                    mma_f16(acc[i][2 * p + 1], Af[i], &Bf[2]);
                }
            }
        }
    }

    // ---- online-exp epilogue (bit-exact order) ----
    const int R0 = wm + g, R1 = wm + g + 8, R2 = wm + 16 + g, R3 = wm + 24 + g;
    const int half = wid >> 2;

    float rm[4] = {-1e30f, -1e30f, -1e30f, -1e30f};
#pragma unroll
    for (int j = 0; j < 8; j++) {
        rm[0] = fmaxf(rm[0], fmaxf(acc[0][j][0], acc[0][j][1]));
        rm[1] = fmaxf(rm[1], fmaxf(acc[0][j][2], acc[0][j][3]));
        rm[2] = fmaxf(rm[2], fmaxf(acc[1][j][0], acc[1][j][1]));
        rm[3] = fmaxf(rm[3], fmaxf(acc[1][j][2], acc[1][j][3]));
    }
#pragma unroll
    for (int o = 1; o <= 2; o <<= 1)
#pragma unroll
        for (int k = 0; k < 4; k++)
            rm[k] = fmaxf(rm[k], __shfl_xor_sync(0xffffffffu, rm[k], o));

    __syncthreads();
    if (t == 0) {
        sred[half][R0] = rm[0]; sred[half][R1] = rm[1];
        sred[half][R2] = rm[2]; sred[half][R3] = rm[3];
    }
    __syncthreads();
    float gm[4];
    gm[0] = fmaxf(sred[0][R0], sred[1][R0]);
    gm[1] = fmaxf(sred[0][R1], sred[1][R1]);
    gm[2] = fmaxf(sred[0][R2], sred[1][R2]);
    gm[3] = fmaxf(sred[0][R3], sred[1][R3]);
    __syncthreads();

    float rs[4] = {0.f, 0.f, 0.f, 0.f};
#pragma unroll
    for (int j = 0; j < 8; j++) {
        acc[0][j][0] = __expf(acc[0][j][0] - gm[0]);
        acc[0][j][1] = __expf(acc[0][j][1] - gm[0]);
        rs[0] += acc[0][j][0] + acc[0][j][1];
        acc[0][j][2] = __expf(acc[0][j][2] - gm[1]);
        acc[0][j][3] = __expf(acc[0][j][3] - gm[1]);
        rs[1] += acc[0][j][2] + acc[0][j][3];
        acc[1][j][0] = __expf(acc[1][j][0] - gm[2]);
        acc[1][j][1] = __expf(acc[1][j][1] - gm[2]);
        rs[2] += acc[1][j][0] + acc[1][j][1];
        acc[1][j][2] = __expf(acc[1][j][2] - gm[3]);
        acc[1][j][3] = __expf(acc[1][j][3] - gm[3]);
        rs[3] += acc[1][j][2] + acc[1][j][3];
    }
#pragma unroll
    for (int o = 1; o <= 2; o <<= 1)
#pragma unroll
        for (int k = 0; k < 4; k++)
            rs[k] += __shfl_xor_sync(0xffffffffu, rs[k], o);

    if (t == 0 && half == 0) {
        sred[0][R0] = rs[0]; sred[0][R1] = rs[1];
        sred[0][R2] = rs[2]; sred[0][R3] = rs[3];
    }
    __syncthreads();
    if (t == 0 && half == 1) {
        atomicAdd(&sred[0][R0], rs[0]); atomicAdd(&sred[0][R1], rs[1]);
        atomicAdd(&sred[0][R2], rs[2]); atomicAdd(&sred[0][R3], rs[3]);
    }
    __syncthreads();

    if (t == 0 && half == 0) {
        const long long sb = ((long long)(bz * NTILE + blockIdx.x) << 10) + m0;
        mloc[sb + R0] = gm[0]; rsum[sb + R0] = sred[0][R0];
        mloc[sb + R1] = gm[1]; rsum[sb + R1] = sred[0][R1];
        mloc[sb + R2] = gm[2]; rsum[sb + R2] = sred[0][R2];
        mloc[sb + R3] = gm[3]; rsum[sb + R3] = sred[0][R3];
    }

    __half* Eb = E + ((long long)bz << 20);
#pragma unroll
    for (int i = 0; i < 2; i++) {
        const int r0 = m0 + wm + i * 16 + g;
#pragma unroll
        for (int j = 0; j < 8; j++) {
            const int cc = n0 + wn + j * 8 + 2 * t;
            *(uint32_t*)(Eb + (long long)r0 * NN + cc) =
                packh2(__float2half_rn(acc[i][j][0]), __float2half_rn(acc[i][j][1]));
            *(uint32_t*)(Eb + (long long)(r0 + 8) * NN + cc) =
                packh2(__float2half_rn(acc[i][j][2]), __float2half_rn(acc[i][j][3]));
        }
    }
}

// ===========================================================================
// O GEMM: O = (diag-scaled E) * Vt^T -> single fp16, stats inlined
// ===========================================================================
__global__ __launch_bounds__(THREADS, 2) void gemm_pv(
    const __half* __restrict__ E, const __half* __restrict__ Vt,
    const float* __restrict__ mloc, const float* __restrict__ rsum,
    __half* __restrict__ O16)
{
    cudaGridDependencySynchronize();   // PDL
    extern __shared__ char smc[];
    __shared__ float sscl[NTILE][128];
    const uint32_t sbase = smem_u32(smc);

    const int tid = threadIdx.x;
    const int wid = tid >> 5;
    const int lane = tid & 31;
    const int g = lane >> 2;
    const int t = lane & 3;
    const int bz = blockIdx.z;

    const __half* Ab = E + ((long long)bz << 20);
    const __half* Bb = Vt + ((long long)bz * HH * NN);
    const int m0 = blockIdx.y * BM;
    const int n0 = blockIdx.x * BN;
    const int wm = (wid & 3) * 32;
    const int wn = (wid >> 2) * 64;
    const int N = HH, K = NN;

    // inline stats (identical op order)
    if (tid < 128) {
        const int r = m0 + tid;
        float m[NTILE], s[NTILE];
        float M = -1e30f;
#pragma unroll
        for (int tt = 0; tt < NTILE; tt++) {
            const long long p = ((long long)(bz * NTILE + tt) << 10) + r;
            m[tt] = mloc[p]; s[tt] = rsum[p];
            M = fmaxf(M, m[tt]);
        }
        float denom = 0.f;
#pragma unroll
        for (int tt = 0; tt < NTILE; tt++) {
            m[tt] = __expf(m[tt] - M);
            denom += s[tt] * m[tt];
        }
        const float inv = 1.0f / denom;
#pragma unroll
        for (int tt = 0; tt < NTILE; tt++)
            sscl[tt][tid] = m[tt] * inv;
    }

    float acc[2][8][4];
#pragma unroll
    for (int i = 0; i < 2; i++)
#pragma unroll
        for (int j = 0; j < 8; j++)
#pragma unroll
            for (int r = 0; r < 4; r++) acc[i][j][r] = 0.0f;

    const int niter = K / BK64;   // 16

#pragma unroll
    for (int it = 0; it < SSTAGES - 1; it++) { ISSUE64(Ab, Bb, K, it); CP_COMMIT(); }
    __syncthreads();   // sscl ready

    const int a_row = lane & 15;
    const int a_kc = (lane >> 4) * 8;
    const int b_n = ((lane >> 4) << 3) + (lane & 7);
    const int b_kc = ((lane >> 3) & 1) * 8;

    const int R0 = wm + g, R1 = wm + g + 8, R2 = wm + 16 + g, R3 = wm + 24 + g;
    __half2 hs[4];

    for (int it = 0; it < niter; it++) {
        CP_WAIT(SSTAGES - 2);
        __syncthreads();
        if (it + SSTAGES - 1 < niter) { ISSUE64(Ab, Bb, K, it + SSTAGES - 1); }
        CP_COMMIT();

        if ((it & 1) == 0) {
            const int tt = it >> 1;
            hs[0] = __float2half2_rn(sscl[tt][R0]);
            hs[1] = __float2half2_rn(sscl[tt][R1]);
            hs[2] = __float2half2_rn(sscl[tt][R2]);
            hs[3] = __float2half2_rn(sscl[tt][R3]);
        }

        const uint32_t stg = sbase + (it % SSTAGES) * SSTAGE_B;
#pragma unroll
        for (int kk = 0; kk < BK64; kk += 16) {
            uint32_t Af[2][4];
#pragma unroll
            for (int i = 0; i < 2; i++) {
                ldsm4(Af[i], stg + (uint32_t)(wm + i * 16 + a_row) * PITCH64
                               + (uint32_t)(kk + a_kc) * 2);
                Af[i][0] = mulh2(Af[i][0], hs[2 * i]);
                Af[i][1] = mulh2(Af[i][1], hs[2 * i + 1]);
                Af[i][2] = mulh2(Af[i][2], hs[2 * i]);
                Af[i][3] = mulh2(Af[i][3], hs[2 * i + 1]);
            }
#pragma unroll
            for (int p = 0; p < 4; p++) {
                uint32_t Bf[4];
                ldsm4(Bf, stg + PLANE64 + (uint32_t)(wn + p * 16 + b_n) * PITCH64
                                        + (uint32_t)(kk + b_kc) * 2);
#pragma unroll
                for (int i = 0; i < 2; i++) {
                    mma_f16(acc[i][2 * p],     Af[i], &Bf[0]);
                    mma_f16(acc[i][2 * p + 1], Af[i], &Bf[2]);
                }
            }
        }
    }

    __half* Ch = O16 + (long long)bz * NN * HH;
#pragma unroll
    for (int i = 0; i < 2; i++) {
        const int r0 = m0 + wm + i * 16 + g;
#pragma unroll
        for (int j = 0; j < 8; j++) {
            const int cc = n0 + wn + j * 8 + 2 * t;
            *(uint32_t*)(Ch + (long long)r0 * N + cc) =
                packh2(__float2half_rn(acc[i][j][0]), __float2half_rn(acc[i][j][1]));
            *(uint32_t*)(Ch + (long long)(r0 + 8) * N + cc) =
                packh2(__float2half_rn(acc[i][j][2]), __float2half_rn(acc[i][j][3]));
        }
    }
}

// ===========================================================================
// Out-proj GEMM (1 MMA): out = relu(o Wo^T + bo), fp32 out. Single plane.
// ===========================================================================
__global__ __launch_bounds__(THREADS, 2) void gemm_out(
    const __half* __restrict__ A, const __half* __restrict__ B,
    const float* __restrict__ bias, float* __restrict__ C,
    int M, int N, int K)
{
    cudaGridDependencySynchronize();   // PDL
    extern __shared__ char smc[];
    const uint32_t sbase = smem_u32(smc);

    const int tid = threadIdx.x;
    const int wid = tid >> 5;
    const int lane = tid & 31;
    const int g = lane >> 2;
    const int t = lane & 3;

    const __half* Ab = A;
    const __half* Bb = B;
    const int m0 = blockIdx.y * BM;
    const int n0 = blockIdx.x * BN;
    const int wm = (wid & 3) * 32;
    const int wn = (wid >> 2) * 64;

    float acc[2][8][4];
#pragma unroll
    for (int i = 0; i < 2; i++)
#pragma unroll
        for (int j = 0; j < 8; j++)
#pragma unroll
            for (int r = 0; r < 4; r++) acc[i][j][r] = 0.0f;

    const int niter = K / BK64;   // 8

#pragma unroll
    for (int it = 0; it < SSTAGES - 1; it++) { ISSUE64(Ab, Bb, K, it); CP_COMMIT(); }

    const int a_row = lane & 15;
    const int a_kc = (lane >> 4) * 8;
    const int b_n = ((lane >> 4) << 3) + (lane & 7);
    const int b_kc = ((lane >> 3) & 1) * 8;

    for (int it = 0; it < niter; it++) {
        CP_WAIT(SSTAGES - 2);
        __syncthreads();
        if (it + SSTAGES - 1 < niter) { ISSUE64(Ab, Bb, K, it + SSTAGES - 1); }
        CP_COMMIT();

        const uint32_t stg = sbase + (it % SSTAGES) * SSTAGE_B;
#pragma unroll
        for (int kk = 0; kk < BK64; kk += 16) {
            uint32_t Af[2][4];
#pragma unroll
            for (int i = 0; i < 2; i++)
                ldsm4(Af[i], stg + (uint32_t)(wm + i * 16 + a_row) * PITCH64
                               + (uint32_t)(kk + a_kc) * 2);
#pragma unroll
            for (int p = 0; p < 4; p++) {
                uint32_t Bf[4];
                ldsm4(Bf, stg + PLANE64 + (uint32_t)(wn + p * 16 + b_n) * PITCH64
                                        + (uint32_t)(kk + b_kc) * 2);
#pragma unroll
                for (int i = 0; i < 2; i++) {
                    mma_f16(acc[i][2 * p],     Af[i], &Bf[0]);
                    mma_f16(acc[i][2 * p + 1], Af[i], &Bf[2]);
                }
            }
        }
    }

#pragma unroll
    for (int i = 0; i < 2; i++) {
        const int r0 = m0 + wm + i * 16 + g;
#pragma unroll
        for (int j = 0; j < 8; j++) {
            const int cc = n0 + wn + j * 8 + 2 * t;
            float b0 = bias[cc], b1 = bias[cc + 1];
            *(float2*)(C + (long long)r0 * N + cc) =
                make_float2(fmaxf(acc[i][j][0] + b0, 0.f), fmaxf(acc[i][j][1] + b1, 0.f));
            *(float2*)(C + (long long)(r0 + 8) * N + cc) =
                make_float2(fmaxf(acc[i][j][2] + b0, 0.f), fmaxf(acc[i][j][3] + b1, 0.f));
        }
    }
}

// ---------------------------------------------------------------------------
// fused pack: h + all 4 weights -> fp16 (single plane each)
// ---------------------------------------------------------------------------
#define PK_H (HB_ELEMS / 4)
#define PK_W (W1_ELEMS / 4)
__global__ __launch_bounds__(256) void pack_all(
    const float* __restrict__ h, const float* __restrict__ Wq,
    const float* __restrict__ Wk, const float* __restrict__ Wv,
    const float* __restrict__ Wo,
    __half* __restrict__ h16, __half* __restrict__ wq16,
    __half* __restrict__ wk16, __half* __restrict__ wv16,
    __half* __restrict__ wo16)
{
    const int total = PK_H + 4 * PK_W;
    for (int i = blockIdx.x * blockDim.x + threadIdx.x; i < total;
         i += gridDim.x * blockDim.x) {
        const float* src; __half* dst; int idx;
        if (i < PK_H) { src = h; dst = h16; idx = i; }
        else {
            int r = i - PK_H;
            int seg = r / PK_W; idx = r % PK_W;
            src = (seg == 0) ? Wq : (seg == 1) ? Wk : (seg == 2) ? Wv : Wo;
            dst = (seg == 0) ? wq16 : (seg == 1) ? wk16 : (seg == 2) ? wv16 : wo16;
        }
        float4 v = ((const float4*)src)[idx];
        ((uint2*)dst)[idx] = make_uint2(
            packh2(__float2half_rn(v.x), __float2half_rn(v.y)),
            packh2(__float2half_rn(v.z), __float2half_rn(v.w)));
    }
}

// ---------------------------------------------------------------------------
// PDL launch helper
// ---------------------------------------------------------------------------
template <typename... Args>
static void launch_pdl(void (*kfn)(Args...), dim3 grid, int smem, Args... args)
{
    cudaLaunchConfig_t cfg = {};
    cfg.gridDim = grid;
    cfg.blockDim = dim3(THREADS, 1, 1);
    cfg.dynamicSmemBytes = (size_t)smem;
    cfg.stream = 0;
    cudaLaunchAttribute attr[1];
    attr[0].id = cudaLaunchAttributeProgrammaticStreamSerialization;
    attr[0].val.programmaticStreamSerializationAllowed = 1;
    cfg.attrs = attr;
    cfg.numAttrs = 1;
    cudaLaunchKernelEx(&cfg, kfn, args...);
}

// ---------------------------------------------------------------------------
// kernel_launch — inputs: h, Wv, bv, Wk, bk, Wq, bq, Wo, bo
// ---------------------------------------------------------------------------
extern "C" void kernel_launch(void* const* d_in, const int* in_sizes, int n_in,
                              void* d_out, int out_size)
{
    const float* h  = (const float*)d_in[0];
    const float* Wv = (const float*)d_in[1];
    const float* bv = (const float*)d_in[2];
    const float* Wk = (const float*)d_in[3];
    const float* bk = (const float*)d_in[4];
    const float* Wq = (const float*)d_in[5];
    const float* bq = (const float*)d_in[6];
    const float* Wo = (const float*)d_in[7];
    const float* bo = (const float*)d_in[8];
    float* out = (float*)d_out;

    __half *h16, *wq16, *wk16, *wv16, *wo16, *q, *k, *vt, *e, *o16;
    float *mloc, *rsum;
    cudaGetSymbolAddress((void**)&h16,  g_h16);
    cudaGetSymbolAddress((void**)&wq16, g_wq16);
    cudaGetSymbolAddress((void**)&wk16, g_wk16);
    cudaGetSymbolAddress((void**)&wv16, g_wv16);
    cudaGetSymbolAddress((void**)&wo16, g_wo16);
    cudaGetSymbolAddress((void**)&q,    g_q);
    cudaGetSymbolAddress((void**)&k,    g_k);
    cudaGetSymbolAddress((void**)&vt,   g_vt);
    cudaGetSymbolAddress((void**)&e,    g_e);
    cudaGetSymbolAddress((void**)&mloc, g_mloc);
    cudaGetSymbolAddress((void**)&rsum, g_rsum);
    cudaGetSymbolAddress((void**)&o16,  g_o16);

    cudaFuncSetAttribute(gemm_proj, cudaFuncAttributeMaxDynamicSharedMemorySize, SSMEM);
    cudaFuncSetAttribute(gemm_qk,   cudaFuncAttributeMaxDynamicSharedMemorySize, SSMEM);
    cudaFuncSetAttribute(gemm_pv,   cudaFuncAttributeMaxDynamicSharedMemorySize, SSMEM);
    cudaFuncSetAttribute(gemm_out,  cudaFuncAttributeMaxDynamicSharedMemorySize, SSMEM);

    const int M = BB * NN;   // 32768

    // 1. fused pack (normal launch)
    pack_all<<<2048, 256>>>(h, Wq, Wk, Wv, Wo, h16, wq16, wk16, wv16, wo16);

    // 2. fused Q/K/V projections; z==2 writes vt directly (PDL)
    launch_pdl(gemm_proj, dim3(HH / BN, M / BM, 3), SSMEM,
               (const __half*)h16, (const __half*)wq16, (const __half*)wk16,
               (const __half*)wv16, bq, bk, bv,
               (__half*)q, (__half*)k, (__half*)vt);

    // 3. S GEMM + online exp -> e fp16 + per-tile stats (PDL)
    launch_pdl(gemm_qk, dim3(NN / BN, NN / BM, BB), SSMEM,
               (const __half*)q, (const __half*)k,
               (__half*)e, (float*)mloc, (float*)rsum);

    // 4. O = scaled-E * Vt^T -> single fp16, stats inlined (PDL)
    launch_pdl(gemm_pv, dim3(HH / BN, NN / BM, BB), SSMEM,
               (const __half*)e, (const __half*)vt,
               (const float*)mloc, (const float*)rsum, (__half*)o16);

    // 5. out = relu(O Wo^T + bo) -> fp32, 1-MMA single-plane GEMM (PDL)
    launch_pdl(gemm_out, dim3(DD / BN, M / BM, 1), SSMEM,
               (const __half*)o16, (const __half*)wo16, bo, out,
               M, DD, HH);
}